// round 11
// baseline (speedup 1.0000x reference)
#include <cuda_runtime.h>
#include <cuda_bf16.h>
#include <cstdint>

#define B_    2
#define CIN_  256
#define COUT_ 256
#define H_    128
#define W_    128
#define HW_   (H_*W_)
#define KK_   3
#define G_    4
#define OCH_  (G_*2*KK_*KK_)   // 72
#define KRED  (CIN_*KK_*KK_)   // 2304
#define NCHUNK (G_*KK_*KK_)    // 36 chunks of 64 k each
#define NPB   (B_*HW_/128)     // 256 pixel tiles

// Scratch buffers
__device__ float g_offset[B_*HW_*OCH_];                  // [pix][72]
__device__ float g_xt[(size_t)B_*HW_*CIN_];              // NHWC: [b][hw][c]
__device__ __nv_bfloat16 g_wb[(size_t)NCHUNK*2*256*64];  // per chunk: [hi 32KB][lo 32KB] swizzled [n][k]

// ---------------------------------------------------------------------------
// helpers
// ---------------------------------------------------------------------------
__device__ __forceinline__ uint32_t smem_u32(const void* p) {
    uint32_t a;
    asm("{ .reg .u64 t; cvta.to.shared.u64 t, %1; cvt.u32.u64 %0, t; }" : "=r"(a) : "l"(p));
    return a;
}
__device__ __forceinline__ void ldsm_x4(uint32_t r[4], uint32_t addr) {
    asm volatile("ldmatrix.sync.aligned.m8n8.x4.shared.b16 {%0,%1,%2,%3}, [%4];"
                 : "=r"(r[0]), "=r"(r[1]), "=r"(r[2]), "=r"(r[3]) : "r"(addr));
}
__device__ __forceinline__ void mma_bf16(float d[4], const uint32_t a[4],
                                         uint32_t b0, uint32_t b1) {
    asm volatile(
        "mma.sync.aligned.m16n8k16.row.col.f32.bf16.bf16.f32 "
        "{%0,%1,%2,%3}, {%4,%5,%6,%7}, {%8,%9}, {%0,%1,%2,%3};"
        : "+f"(d[0]), "+f"(d[1]), "+f"(d[2]), "+f"(d[3])
        : "r"(a[0]), "r"(a[1]), "r"(a[2]), "r"(a[3]), "r"(b0), "r"(b1));
}
__device__ __forceinline__ void mbar_init(uint32_t mbar, uint32_t cnt) {
    asm volatile("mbarrier.init.shared.b64 [%0], %1;" :: "r"(mbar), "r"(cnt) : "memory");
}
__device__ __forceinline__ void mbar_expect_tx(uint32_t mbar, uint32_t bytes) {
    asm volatile("mbarrier.arrive.expect_tx.shared.b64 _, [%0], %1;"
                 :: "r"(mbar), "r"(bytes) : "memory");
}
__device__ __forceinline__ void mbar_wait(uint32_t mbar, uint32_t parity) {
    asm volatile(
        "{\n\t.reg .pred P;\n\t"
        "WL_%=:\n\t"
        "mbarrier.try_wait.parity.acquire.cta.shared::cta.b64 P, [%0], %1, 0x989680;\n\t"
        "@P bra.uni WD_%=;\n\t"
        "bra.uni WL_%=;\n\t"
        "WD_%=:\n\t}"
        :: "r"(mbar), "r"(parity) : "memory");
}
__device__ __forceinline__ void bulk_copy(uint32_t dst, const void* src, uint32_t bytes,
                                          uint32_t mbar) {
    asm volatile(
        "cp.async.bulk.shared::cta.global.mbarrier::complete_tx::bytes [%0], [%1], %2, [%3];"
        :: "r"(dst), "l"(src), "r"(bytes), "r"(mbar) : "memory");
}

// ---------------------------------------------------------------------------
// Kernel A: NCHW -> NHWC transpose (32x32 tiles)
// ---------------------------------------------------------------------------
__global__ void __launch_bounds__(256) transpose_kernel(const float* __restrict__ x,
                                                        float* __restrict__ xt)
{
    __shared__ float tl[32][33];
    const int tx = threadIdx.x, ty = threadIdx.y;
    const int bb = blockIdx.z;
    const int hw0 = blockIdx.x * 32;
    const int c0  = blockIdx.y * 32;
#pragma unroll
    for (int r = 0; r < 4; r++)
        tl[ty + 8*r][tx] = x[((size_t)bb*CIN_ + c0 + ty + 8*r)*HW_ + hw0 + tx];
    __syncthreads();
#pragma unroll
    for (int r = 0; r < 4; r++)
        xt[((size_t)bb*HW_ + hw0 + ty + 8*r)*CIN_ + c0 + tx] = tl[tx][ty + 8*r];
}

// ---------------------------------------------------------------------------
// Kernel B: weight prepack -> bf16 hi/lo, [n][k] tiles, SW128 swizzled.
// ---------------------------------------------------------------------------
__global__ void __launch_bounds__(256) prepack_kernel(const float* __restrict__ wd,
                                                      __nv_bfloat16* __restrict__ wb)
{
    const int gt = blockIdx.x;
    const int g = gt / 9;
    const int tap = gt - 9*g;
    for (int idx = threadIdx.x; idx < 256*64; idx += 256) {
        const int n  = idx >> 6;
        const int cg = idx & 63;
        float v = wd[(size_t)n*KRED + (g*64 + cg)*9 + tap];
        __nv_bfloat16 h = __float2bfloat16_rn(v);
        __nv_bfloat16 l = __float2bfloat16_rn(v - __bfloat162float(h));
        const int dst = n*64 + (cg ^ ((n & 7) << 3));   // SW128 (bf16 elems)
        wb[(size_t)gt*32768 + dst]          = h;
        wb[(size_t)gt*32768 + 16384 + dst]  = l;
    }
}

// ---------------------------------------------------------------------------
// Kernel C: 1x1 offset conv (fp32)
// ---------------------------------------------------------------------------
__global__ void __launch_bounds__(256) offset_kernel(
    const float* __restrict__ x,
    const float* __restrict__ w,
    const float* __restrict__ bias)
{
    __shared__ float xs[16][64];
    __shared__ float ws[72][16];

    const int t    = threadIdx.x;
    const int pix0 = blockIdx.x * 64;
    const int b    = pix0 >> 14;
    const int rem  = pix0 & (HW_-1);
    const int hh   = rem >> 7;
    const int w0   = rem & (W_-1);

    const int p  = t & 63;
    const int oq = t >> 6;

    float acc[18];
#pragma unroll
    for (int i = 0; i < 18; i++) acc[i] = 0.f;

    const float* xbase = x + (size_t)b * CIN_ * HW_ + hh * W_ + w0;

    for (int c0 = 0; c0 < CIN_; c0 += 16) {
#pragma unroll
        for (int r = 0; r < 4; r++) {
            int e  = t + r * 256;
            int kk = e >> 6;
            int pp = e & 63;
            xs[kk][pp] = xbase[(size_t)(c0 + kk) * HW_ + pp];
        }
        for (int e = t; e < 72 * 16; e += 256) {
            int o  = e >> 4;
            int kk = e & 15;
            ws[o][kk] = w[o * CIN_ + c0 + kk];
        }
        __syncthreads();
#pragma unroll
        for (int kk = 0; kk < 16; kk++) {
            float xv = xs[kk][p];
#pragma unroll
            for (int i = 0; i < 18; i++)
                acc[i] = fmaf(xv, ws[oq * 18 + i][kk], acc[i]);
        }
        __syncthreads();
    }

    float* ob = g_offset + (size_t)(pix0 + p) * OCH_;
#pragma unroll
    for (int i = 0; i < 18; i++) {
        int o = oq * 18 + i;
        ob[o] = acc[i] + bias[o];
    }
}

// ---------------------------------------------------------------------------
// Kernel D (fused): deformable conv — in-CTA gather + HMMA GEMM.
// 128 pix x 256 cout per block, 512 threads (16 warps = 4m x 4n, warp 32x64).
// Per chunk: all threads gather A(gt+1) (bilinear, bf16 hi/lo, swizzled STS)
// into the spare stage while B(gt+1) arrives via cp.async.bulk; then MMA gt.
// Stage = Ah 16K | Al 16K | Bh 32K | Bl 32K = 96KB, 2 stages.
// ---------------------------------------------------------------------------
#define FS_AH 0
#define FS_AL 16384
#define FS_BH 32768
#define FS_BL 65536
#define FSTAGE 98304
#define FS_IDX  (2*FSTAGE)            // sidx[4][128] ints (2KB)
#define FS_WGT  (FS_IDX + 2048)       // swgt[4][128] floats (2KB)
#define FS_MBAR (FS_WGT + 2048)       // two 8-byte mbarriers
#define FSMEM   (FS_MBAR + 16)

__global__ void __launch_bounds__(512, 1)
fused_kernel(const float* __restrict__ xt,
             const __nv_bfloat16* __restrict__ wb,
             float* __restrict__ out)
{
    extern __shared__ char sm[];
    const uint32_t sb = smem_u32(sm);

    const int t = threadIdx.x;
    const int warp = t >> 5, lane = t & 31;
    const int pb   = blockIdx.x;
    const int pix0 = pb * 128;
    const int b    = pix0 >> 14;
    const int hw0  = pix0 & (HW_-1);
    const int hh   = hw0 >> 7;

    int*   sidx = (int*)(sm + FS_IDX);
    float* swgt = (float*)(sm + FS_WGT);

    if (t == 0) {
        mbar_init(sb + FS_MBAR, 1);
        mbar_init(sb + FS_MBAR + 8, 1);
    }
    __syncthreads();

    // fragment geometry (R9)
    const int wm = warp & 3, wn = warp >> 2;
    const uint32_t rowA = wm*32 + (lane & 15);
    const uint32_t swzA = (rowA & 7) << 4;
    const uint32_t kA   = (uint32_t)(lane & 16);
    const uint32_t aRow = rowA * 128;
    const uint32_t rowB = wn*64 + (lane & 7) + ((lane & 16) >> 1);
    const uint32_t swzB = (rowB & 7) << 4;
    const uint32_t kB   = (uint32_t)((lane & 8) << 1);
    const uint32_t bRow = rowB * 128;

    // gather geometry: 4 items/thread
    const int slot = t & 15;          // 4-channel slot within 64
    const int gp   = t >> 4;          // 0..31
    const float* xb = xt + (size_t)b * HW_ * CIN_;

    float acc[2][8][4];
#pragma unroll
    for (int i = 0; i < 2; i++)
#pragma unroll
        for (int j = 0; j < 8; j++)
#pragma unroll
            for (int q = 0; q < 4; q++) acc[i][j][q] = 0.f;

    // ---- helpers as lambdas ----
    auto setup_sidx = [&](int gt) {
        if (t < 128) {
            const int g   = gt / 9;
            const int tap = gt - 9*g;
            const int ti  = tap / 3;
            const int tj  = tap - 3*ti;
            const float* op = g_offset + (size_t)(pix0 + t) * OCH_ + gt*2;
            float ys = (float)(hh - 1 + ti) + op[0];
            float xs = (float)(t  - 1 + tj) + op[1];
            float y0f = floorf(ys), x0f = floorf(xs);
            int   y0  = (int)y0f,   x0  = (int)x0f;
            float ly = ys - y0f, lx = xs - x0f;
            float hy = 1.f - ly, hx = 1.f - lx;
            int y1 = y0 + 1, x1 = x0 + 1;
            bool vy0 = (unsigned)y0 < H_, vy1 = (unsigned)y1 < H_;
            bool vx0 = (unsigned)x0 < W_, vx1 = (unsigned)x1 < W_;
            int cy0 = min(max(y0,0),H_-1), cy1 = min(max(y1,0),H_-1);
            int cx0 = min(max(x0,0),W_-1), cx1 = min(max(x1,0),W_-1);
            sidx[0*128 + t] = cy0*W_ + cx0;
            sidx[1*128 + t] = cy0*W_ + cx1;
            sidx[2*128 + t] = cy1*W_ + cx0;
            sidx[3*128 + t] = cy1*W_ + cx1;
            swgt[0*128 + t] = (vy0 && vx0) ? hy*hx : 0.f;
            swgt[1*128 + t] = (vy0 && vx1) ? hy*lx : 0.f;
            swgt[2*128 + t] = (vy1 && vx0) ? ly*hx : 0.f;
            swgt[3*128 + t] = (vy1 && vx1) ? ly*lx : 0.f;
        }
    };

    auto gather = [&](int gt, uint32_t stage_base_off) {
        const int g   = gt / 9;
        const int gch = g * 64;
        const int co  = gch + slot*4;
        char* smc = sm + stage_base_off;
#pragma unroll
        for (int pass = 0; pass < 4; pass++) {
            const int p  = pass*32 + gp;
            const int i0 = sidx[0*128+p], i1 = sidx[1*128+p];
            const int i2 = sidx[2*128+p], i3 = sidx[3*128+p];
            const float w0 = swgt[0*128+p], w1 = swgt[1*128+p];
            const float w2 = swgt[2*128+p], w3 = swgt[3*128+p];
            float4 v0 = *(const float4*)(xb + (size_t)i0*CIN_ + co);
            float4 v1 = *(const float4*)(xb + (size_t)i1*CIN_ + co);
            float4 v2 = *(const float4*)(xb + (size_t)i2*CIN_ + co);
            float4 v3 = *(const float4*)(xb + (size_t)i3*CIN_ + co);
            float r0 = fmaf(w3,v3.x, fmaf(w2,v2.x, fmaf(w1,v1.x, w0*v0.x)));
            float r1 = fmaf(w3,v3.y, fmaf(w2,v2.y, fmaf(w1,v1.y, w0*v0.y)));
            float r2 = fmaf(w3,v3.z, fmaf(w2,v2.z, fmaf(w1,v1.z, w0*v0.z)));
            float r3 = fmaf(w3,v3.w, fmaf(w2,v2.w, fmaf(w1,v1.w, w0*v0.w)));

            __nv_bfloat16 h0 = __float2bfloat16_rn(r0);
            __nv_bfloat16 h1 = __float2bfloat16_rn(r1);
            __nv_bfloat16 h2 = __float2bfloat16_rn(r2);
            __nv_bfloat16 h3 = __float2bfloat16_rn(r3);
            __nv_bfloat16 l0 = __float2bfloat16_rn(r0 - __bfloat162float(h0));
            __nv_bfloat16 l1 = __float2bfloat16_rn(r1 - __bfloat162float(h1));
            __nv_bfloat16 l2 = __float2bfloat16_rn(r2 - __bfloat162float(h2));
            __nv_bfloat16 l3 = __float2bfloat16_rn(r3 - __bfloat162float(h3));

            const uint32_t aoff = (uint32_t)(p*128 + ((slot*8) ^ ((p & 7) << 4)));
            __nv_bfloat162 hA(h0, h1), hB(h2, h3), lA(l0, l1), lB(l2, l3);
            uint2 hv, lv;
            hv.x = *(uint32_t*)&hA; hv.y = *(uint32_t*)&hB;
            lv.x = *(uint32_t*)&lA; lv.y = *(uint32_t*)&lB;
            *(uint2*)(smc + FS_AH + aoff) = hv;
            *(uint2*)(smc + FS_AL + aoff) = lv;
        }
    };

    // ---- prologue: stage 0 = chunk 0 ----
    setup_sidx(0);
    __syncthreads();
    if (t == 0) {
        mbar_expect_tx(sb + FS_MBAR, 65536);
        bulk_copy(sb + FS_BH, (const char*)wb, 65536, sb + FS_MBAR);
    }
    gather(0, 0);

    for (int gt = 0; gt < NCHUNK; gt++) {
        const int s = gt & 1;
        const uint32_t cur = sb + s * FSTAGE;

        // all warps have finished MMA(gt-1) (stage s^1) and gather(gt)
        __syncthreads();

        if (gt + 1 < NCHUNK) {
            setup_sidx(gt + 1);
            __syncthreads();          // sidx ready for everyone
            if (t == 0) {
                uint32_t mb = sb + FS_MBAR + ((gt + 1) & 1) * 8;
                mbar_expect_tx(mb, 65536);
                bulk_copy(sb + ((gt + 1) & 1) * FSTAGE + FS_BH,
                          (const char*)wb + (size_t)(gt + 1) * 65536, 65536, mb);
            }
            gather(gt + 1, ((gt + 1) & 1) * FSTAGE);
        }

        mbar_wait(sb + FS_MBAR + s * 8, (gt >> 1) & 1);

        // 4 k-steps; fragment-reuse order: hi*hi -> lo*hi -> hi*lo
#pragma unroll
        for (int ks = 0; ks < 4; ks++) {
            const uint32_t kbyte = (uint32_t)(ks * 32);
            const uint32_t aoff = (kbyte + kA) ^ swzA;
            const uint32_t boff = (kbyte + kB) ^ swzB;

            uint32_t bfr[4][4], ah[2][4], al[2][4];

#pragma unroll
            for (int np = 0; np < 4; np++)
                ldsm_x4(bfr[np], cur + FS_BH + bRow + np*2048 + boff);
#pragma unroll
            for (int mt = 0; mt < 2; mt++)
                ldsm_x4(ah[mt], cur + FS_AH + aRow + mt*2048 + aoff);

#pragma unroll
            for (int mt = 0; mt < 2; mt++)
#pragma unroll
                for (int nt = 0; nt < 8; nt++)
                    mma_bf16(acc[mt][nt], ah[mt],
                             bfr[nt >> 1][(nt & 1) * 2],
                             bfr[nt >> 1][(nt & 1) * 2 + 1]);

#pragma unroll
            for (int mt = 0; mt < 2; mt++)
                ldsm_x4(al[mt], cur + FS_AL + aRow + mt*2048 + aoff);
#pragma unroll
            for (int mt = 0; mt < 2; mt++)
#pragma unroll
                for (int nt = 0; nt < 8; nt++)
                    mma_bf16(acc[mt][nt], al[mt],
                             bfr[nt >> 1][(nt & 1) * 2],
                             bfr[nt >> 1][(nt & 1) * 2 + 1]);

            // B_lo lives at FS_BL = FS_BH + 32768 (R10 bug: used +16384)
#pragma unroll
            for (int np = 0; np < 4; np++)
                ldsm_x4(bfr[np], cur + FS_BL + bRow + np*2048 + boff);
#pragma unroll
            for (int mt = 0; mt < 2; mt++)
#pragma unroll
                for (int nt = 0; nt < 8; nt++)
                    mma_bf16(acc[mt][nt], ah[mt],
                             bfr[nt >> 1][(nt & 1) * 2],
                             bfr[nt >> 1][(nt & 1) * 2 + 1]);
        }
    }

    // ---- epilogue: relu + store (NCHW) ----
    const size_t ob = (size_t)b * COUT_ * HW_ + hw0;
    const int mrow = wm*32 + (lane >> 2);
    const int ncol = wn*64 + (lane & 3) * 2;
#pragma unroll
    for (int mt = 0; mt < 2; mt++) {
#pragma unroll
        for (int nt = 0; nt < 8; nt++) {
            const int m = mrow + mt*16;
            const int n = ncol + nt*8;
            float* o0 = out + ob + (size_t)n * HW_ + m;
            o0[0]        = fmaxf(acc[mt][nt][0], 0.f);
            o0[HW_]      = fmaxf(acc[mt][nt][1], 0.f);
            o0[8]        = fmaxf(acc[mt][nt][2], 0.f);
            o0[HW_ + 8]  = fmaxf(acc[mt][nt][3], 0.f);
        }
    }
}

// ---------------------------------------------------------------------------
extern "C" void kernel_launch(void* const* d_in, const int* in_sizes, int n_in,
                              void* d_out, int out_size)
{
    (void)in_sizes; (void)n_in; (void)out_size;
    const float* x     = (const float*)d_in[0];
    const float* w_off = (const float*)d_in[1];
    const float* b_off = (const float*)d_in[2];
    const float* w_def = (const float*)d_in[3];
    float* out = (float*)d_out;

    float* xt;           cudaGetSymbolAddress((void**)&xt, g_xt);
    __nv_bfloat16* wbp;  cudaGetSymbolAddress((void**)&wbp, g_wb);

    transpose_kernel<<<dim3(HW_/32, CIN_/32, B_), dim3(32, 8)>>>(x, xt);
    prepack_kernel<<<NCHUNK, 256>>>(w_def, wbp);
    offset_kernel<<<B_*HW_/64, 256>>>(x, w_off, b_off);

    static bool attr_set = false;
    if (!attr_set) {
        cudaFuncSetAttribute(fused_kernel,
                             cudaFuncAttributeMaxDynamicSharedMemorySize, FSMEM);
        attr_set = true;
    }
    fused_kernel<<<NPB, 512, FSMEM>>>(xt, wbp, out);
}

// round 12
// speedup vs baseline: 1.0207x; 1.0207x over previous
#include <cuda_runtime.h>
#include <cuda_bf16.h>
#include <cstdint>

#define B_    2
#define CIN_  256
#define COUT_ 256
#define H_    128
#define W_    128
#define HW_   (H_*W_)
#define KK_   3
#define G_    4
#define OCH_  (G_*2*KK_*KK_)   // 72
#define KRED  (CIN_*KK_*KK_)   // 2304
#define NCHUNK (G_*KK_*KK_)    // 36 chunks of 64 k each
#define NPB   (B_*HW_/128)     // 256 pixel tiles

// Scratch buffers
__device__ float g_offset[B_*HW_*OCH_];                  // [pix][72]
__device__ float g_xt[(size_t)B_*HW_*CIN_];              // NHWC: [b][hw][c]
__device__ __nv_bfloat16 g_wb[(size_t)NCHUNK*2*256*64];  // per chunk: [hi 32KB][lo 32KB] swizzled [n][k]

// ---------------------------------------------------------------------------
// helpers
// ---------------------------------------------------------------------------
__device__ __forceinline__ uint32_t smem_u32(const void* p) {
    uint32_t a;
    asm("{ .reg .u64 t; cvta.to.shared.u64 t, %1; cvt.u32.u64 %0, t; }" : "=r"(a) : "l"(p));
    return a;
}
__device__ __forceinline__ void ldsm_x4(uint32_t r[4], uint32_t addr) {
    asm volatile("ldmatrix.sync.aligned.m8n8.x4.shared.b16 {%0,%1,%2,%3}, [%4];"
                 : "=r"(r[0]), "=r"(r[1]), "=r"(r[2]), "=r"(r[3]) : "r"(addr));
}
__device__ __forceinline__ void mma_bf16(float d[4], const uint32_t a[4],
                                         uint32_t b0, uint32_t b1) {
    asm volatile(
        "mma.sync.aligned.m16n8k16.row.col.f32.bf16.bf16.f32 "
        "{%0,%1,%2,%3}, {%4,%5,%6,%7}, {%8,%9}, {%0,%1,%2,%3};"
        : "+f"(d[0]), "+f"(d[1]), "+f"(d[2]), "+f"(d[3])
        : "r"(a[0]), "r"(a[1]), "r"(a[2]), "r"(a[3]), "r"(b0), "r"(b1));
}
__device__ __forceinline__ void mbar_init(uint32_t mbar, uint32_t cnt) {
    asm volatile("mbarrier.init.shared.b64 [%0], %1;" :: "r"(mbar), "r"(cnt) : "memory");
}
__device__ __forceinline__ void mbar_expect_tx(uint32_t mbar, uint32_t bytes) {
    asm volatile("mbarrier.arrive.expect_tx.shared.b64 _, [%0], %1;"
                 :: "r"(mbar), "r"(bytes) : "memory");
}
__device__ __forceinline__ void mbar_wait(uint32_t mbar, uint32_t parity) {
    asm volatile(
        "{\n\t.reg .pred P;\n\t"
        "WL_%=:\n\t"
        "mbarrier.try_wait.parity.acquire.cta.shared::cta.b64 P, [%0], %1, 0x989680;\n\t"
        "@P bra.uni WD_%=;\n\t"
        "bra.uni WL_%=;\n\t"
        "WD_%=:\n\t}"
        :: "r"(mbar), "r"(parity) : "memory");
}
__device__ __forceinline__ void bulk_copy(uint32_t dst, const void* src, uint32_t bytes,
                                          uint32_t mbar) {
    asm volatile(
        "cp.async.bulk.shared::cta.global.mbarrier::complete_tx::bytes [%0], [%1], %2, [%3];"
        :: "r"(dst), "l"(src), "r"(bytes), "r"(mbar) : "memory");
}

// ---------------------------------------------------------------------------
// Kernel A: NCHW -> NHWC transpose (32x32 tiles)
// ---------------------------------------------------------------------------
__global__ void __launch_bounds__(256) transpose_kernel(const float* __restrict__ x,
                                                        float* __restrict__ xt)
{
    __shared__ float tl[32][33];
    const int tx = threadIdx.x, ty = threadIdx.y;
    const int bb = blockIdx.z;
    const int hw0 = blockIdx.x * 32;
    const int c0  = blockIdx.y * 32;
#pragma unroll
    for (int r = 0; r < 4; r++)
        tl[ty + 8*r][tx] = x[((size_t)bb*CIN_ + c0 + ty + 8*r)*HW_ + hw0 + tx];
    __syncthreads();
#pragma unroll
    for (int r = 0; r < 4; r++)
        xt[((size_t)bb*HW_ + hw0 + ty + 8*r)*CIN_ + c0 + tx] = tl[tx][ty + 8*r];
}

// ---------------------------------------------------------------------------
// Kernel B: weight prepack -> bf16 hi/lo, [n][k] tiles, SW128 swizzled.
// ---------------------------------------------------------------------------
__global__ void __launch_bounds__(256) prepack_kernel(const float* __restrict__ wd,
                                                      __nv_bfloat16* __restrict__ wb)
{
    const int gt = blockIdx.x;
    const int g = gt / 9;
    const int tap = gt - 9*g;
    for (int idx = threadIdx.x; idx < 256*64; idx += 256) {
        const int n  = idx >> 6;
        const int cg = idx & 63;
        float v = wd[(size_t)n*KRED + (g*64 + cg)*9 + tap];
        __nv_bfloat16 h = __float2bfloat16_rn(v);
        __nv_bfloat16 l = __float2bfloat16_rn(v - __bfloat162float(h));
        const int dst = n*64 + (cg ^ ((n & 7) << 3));   // SW128 (bf16 elems)
        wb[(size_t)gt*32768 + dst]          = h;
        wb[(size_t)gt*32768 + 16384 + dst]  = l;
    }
}

// ---------------------------------------------------------------------------
// Kernel C: 1x1 offset conv (fp32)
// ---------------------------------------------------------------------------
__global__ void __launch_bounds__(256) offset_kernel(
    const float* __restrict__ x,
    const float* __restrict__ w,
    const float* __restrict__ bias)
{
    __shared__ float xs[16][64];
    __shared__ float ws[72][16];

    const int t    = threadIdx.x;
    const int pix0 = blockIdx.x * 64;
    const int b    = pix0 >> 14;
    const int rem  = pix0 & (HW_-1);
    const int hh   = rem >> 7;
    const int w0   = rem & (W_-1);

    const int p  = t & 63;
    const int oq = t >> 6;

    float acc[18];
#pragma unroll
    for (int i = 0; i < 18; i++) acc[i] = 0.f;

    const float* xbase = x + (size_t)b * CIN_ * HW_ + hh * W_ + w0;

    for (int c0 = 0; c0 < CIN_; c0 += 16) {
#pragma unroll
        for (int r = 0; r < 4; r++) {
            int e  = t + r * 256;
            int kk = e >> 6;
            int pp = e & 63;
            xs[kk][pp] = xbase[(size_t)(c0 + kk) * HW_ + pp];
        }
        for (int e = t; e < 72 * 16; e += 256) {
            int o  = e >> 4;
            int kk = e & 15;
            ws[o][kk] = w[o * CIN_ + c0 + kk];
        }
        __syncthreads();
#pragma unroll
        for (int kk = 0; kk < 16; kk++) {
            float xv = xs[kk][p];
#pragma unroll
            for (int i = 0; i < 18; i++)
                acc[i] = fmaf(xv, ws[oq * 18 + i][kk], acc[i]);
        }
        __syncthreads();
    }

    float* ob = g_offset + (size_t)(pix0 + p) * OCH_;
#pragma unroll
    for (int i = 0; i < 18; i++) {
        int o = oq * 18 + i;
        ob[o] = acc[i] + bias[o];
    }
}

// ---------------------------------------------------------------------------
// Kernel D (fused): deformable conv — gather interleaved with HMMA GEMM.
// 128 pix x 256 cout per block, 512 threads (16 warps = 4m x 4n, warp 32x64).
// Per chunk gt: MMA(gt) from stage s while gathering A(gt+1) into stage s^1,
// with each gather pass's LDGs issued BEFORE one MMA k-step (latency hiding);
// B(gt+1) arrives via cp.async.bulk. sidx/swgt double-buffered (setup for
// gt+2 done one iteration early) -> single __syncthreads per chunk.
// Stage = Ah 16K | Al 16K | Bh 32K | Bl 32K = 96KB, 2 stages.
// ---------------------------------------------------------------------------
#define FS_AH 0
#define FS_AL 16384
#define FS_BH 32768
#define FS_BL 65536
#define FSTAGE 98304
#define FS_IDX  (2*FSTAGE)            // sidx[2][4][128] ints (4KB)
#define FS_WGT  (FS_IDX + 4096)       // swgt[2][4][128] floats (4KB)
#define FS_MBAR (FS_WGT + 4096)       // two 8-byte mbarriers
#define FSMEM   (FS_MBAR + 16)

__global__ void __launch_bounds__(512, 1)
fused_kernel(const float* __restrict__ xt,
             const __nv_bfloat16* __restrict__ wb,
             float* __restrict__ out)
{
    extern __shared__ char sm[];
    const uint32_t sb = smem_u32(sm);

    const int t = threadIdx.x;
    const int warp = t >> 5, lane = t & 31;
    const int pb   = blockIdx.x;
    const int pix0 = pb * 128;
    const int b    = pix0 >> 14;
    const int hw0  = pix0 & (HW_-1);
    const int hh   = hw0 >> 7;

    int*   sidx = (int*)(sm + FS_IDX);     // [buf][4][128]
    float* swgt = (float*)(sm + FS_WGT);   // [buf][4][128]

    if (t == 0) {
        mbar_init(sb + FS_MBAR, 1);
        mbar_init(sb + FS_MBAR + 8, 1);
    }
    __syncthreads();

    // fragment geometry (R9)
    const int wm = warp & 3, wn = warp >> 2;
    const uint32_t rowA = wm*32 + (lane & 15);
    const uint32_t swzA = (rowA & 7) << 4;
    const uint32_t kA   = (uint32_t)(lane & 16);
    const uint32_t aRow = rowA * 128;
    const uint32_t rowB = wn*64 + (lane & 7) + ((lane & 16) >> 1);
    const uint32_t swzB = (rowB & 7) << 4;
    const uint32_t kB   = (uint32_t)((lane & 8) << 1);
    const uint32_t bRow = rowB * 128;

    // gather geometry: 4 items/thread (one per pass)
    const int slot = t & 15;          // 4-channel slot within 64
    const int gp   = t >> 4;          // 0..31
    const float* xb = xt + (size_t)b * HW_ * CIN_;

    float acc[2][8][4];
#pragma unroll
    for (int i = 0; i < 2; i++)
#pragma unroll
        for (int j = 0; j < 8; j++)
#pragma unroll
            for (int q = 0; q < 4; q++) acc[i][j][q] = 0.f;

    auto setup_sidx = [&](int gt, int buf) {
        if (t < 128 && gt < NCHUNK) {
            const int g   = gt / 9;
            const int tap = gt - 9*g;
            const int ti  = tap / 3;
            const int tj  = tap - 3*ti;
            const float* op = g_offset + (size_t)(pix0 + t) * OCH_ + gt*2;
            float ys = (float)(hh - 1 + ti) + op[0];
            float xs = (float)(t  - 1 + tj) + op[1];
            float y0f = floorf(ys), x0f = floorf(xs);
            int   y0  = (int)y0f,   x0  = (int)x0f;
            float ly = ys - y0f, lx = xs - x0f;
            float hy = 1.f - ly, hx = 1.f - lx;
            int y1 = y0 + 1, x1 = x0 + 1;
            bool vy0 = (unsigned)y0 < H_, vy1 = (unsigned)y1 < H_;
            bool vx0 = (unsigned)x0 < W_, vx1 = (unsigned)x1 < W_;
            int cy0 = min(max(y0,0),H_-1), cy1 = min(max(y1,0),H_-1);
            int cx0 = min(max(x0,0),W_-1), cx1 = min(max(x1,0),W_-1);
            int* si = sidx + buf*512;
            float* sw = swgt + buf*512;
            si[0*128 + t] = cy0*W_ + cx0;
            si[1*128 + t] = cy0*W_ + cx1;
            si[2*128 + t] = cy1*W_ + cx0;
            si[3*128 + t] = cy1*W_ + cx1;
            sw[0*128 + t] = (vy0 && vx0) ? hy*hx : 0.f;
            sw[1*128 + t] = (vy0 && vx1) ? hy*lx : 0.f;
            sw[2*128 + t] = (vy1 && vx0) ? ly*hx : 0.f;
            sw[3*128 + t] = (vy1 && vx1) ? ly*lx : 0.f;
        }
    };

    // single gather pass: load -> combine -> split -> swizzled STS
    auto gather_pass = [&](int pass, int gt, int buf, uint32_t stage_off) {
        const int g   = gt / 9;
        const int co  = g*64 + slot*4;
        const int p   = pass*32 + gp;
        const int* si = sidx + buf*512;
        const float* sw = swgt + buf*512;
        const int i0 = si[0*128+p], i1 = si[1*128+p];
        const int i2 = si[2*128+p], i3 = si[3*128+p];
        const float w0 = sw[0*128+p], w1 = sw[1*128+p];
        const float w2 = sw[2*128+p], w3 = sw[3*128+p];
        float4 v0 = *(const float4*)(xb + (size_t)i0*CIN_ + co);
        float4 v1 = *(const float4*)(xb + (size_t)i1*CIN_ + co);
        float4 v2 = *(const float4*)(xb + (size_t)i2*CIN_ + co);
        float4 v3 = *(const float4*)(xb + (size_t)i3*CIN_ + co);
        float r0 = fmaf(w3,v3.x, fmaf(w2,v2.x, fmaf(w1,v1.x, w0*v0.x)));
        float r1 = fmaf(w3,v3.y, fmaf(w2,v2.y, fmaf(w1,v1.y, w0*v0.y)));
        float r2 = fmaf(w3,v3.z, fmaf(w2,v2.z, fmaf(w1,v1.z, w0*v0.z)));
        float r3 = fmaf(w3,v3.w, fmaf(w2,v2.w, fmaf(w1,v1.w, w0*v0.w)));
        __nv_bfloat16 h0 = __float2bfloat16_rn(r0);
        __nv_bfloat16 h1 = __float2bfloat16_rn(r1);
        __nv_bfloat16 h2 = __float2bfloat16_rn(r2);
        __nv_bfloat16 h3 = __float2bfloat16_rn(r3);
        __nv_bfloat16 l0 = __float2bfloat16_rn(r0 - __bfloat162float(h0));
        __nv_bfloat16 l1 = __float2bfloat16_rn(r1 - __bfloat162float(h1));
        __nv_bfloat16 l2 = __float2bfloat16_rn(r2 - __bfloat162float(h2));
        __nv_bfloat16 l3 = __float2bfloat16_rn(r3 - __bfloat162float(h3));
        const uint32_t aoff = (uint32_t)(p*128 + ((slot*8) ^ ((p & 7) << 4)));
        __nv_bfloat162 hA(h0, h1), hB(h2, h3), lA(l0, l1), lB(l2, l3);
        uint2 hv, lv;
        hv.x = *(uint32_t*)&hA; hv.y = *(uint32_t*)&hB;
        lv.x = *(uint32_t*)&lA; lv.y = *(uint32_t*)&lB;
        char* smc = sm + stage_off;
        *(uint2*)(smc + FS_AH + aoff) = hv;
        *(uint2*)(smc + FS_AL + aoff) = lv;
    };

    // ---- prologue ----
    setup_sidx(0, 0);
    __syncthreads();
    if (t == 0) {
        mbar_expect_tx(sb + FS_MBAR, 65536);
        bulk_copy(sb + FS_BH, (const char*)wb, 65536, sb + FS_MBAR);
    }
    setup_sidx(1, 1);
#pragma unroll
    for (int pass = 0; pass < 4; pass++)
        gather_pass(pass, 0, 0, 0);

    for (int gt = 0; gt < NCHUNK; gt++) {
        const int s = gt & 1;
        const uint32_t cur = sb + s * FSTAGE;
        const int nxt = gt + 1;
        const bool pre = (nxt < NCHUNK);

        // gather(gt) STS visible; MMA(gt-1) done -> stage s^1 reusable;
        // setup(gt+1) from previous iteration visible
        __syncthreads();

        if (pre && t == 0) {
            uint32_t mb = sb + FS_MBAR + (nxt & 1) * 8;
            mbar_expect_tx(mb, 65536);
            bulk_copy(sb + (nxt & 1) * FSTAGE + FS_BH,
                      (const char*)wb + (size_t)nxt * 65536, 65536, mb);
        }
        setup_sidx(gt + 2, gt & 1);   // buf (gt+2)&1 == gt&1, free since last iter

        mbar_wait(sb + FS_MBAR + s * 8, (gt >> 1) & 1);

        const uint32_t nxt_off = (uint32_t)((nxt & 1) * FSTAGE);

        // 4 k-steps, each fronted by one gather pass for chunk gt+1
#pragma unroll
        for (int ks = 0; ks < 4; ks++) {
            const uint32_t kbyte = (uint32_t)(ks * 32);
            const uint32_t aoff = (kbyte + kA) ^ swzA;
            const uint32_t boff = (kbyte + kB) ^ swzB;

            // ---- gather pass ks (loads issued here, long-latency) ----
            float4 v0, v1, v2, v3;
            float w0, w1, w2, w3;
            int p = ks*32 + gp;
            if (pre) {
                const int g   = nxt / 9;
                const int co  = g*64 + slot*4;
                const int* si = sidx + (nxt & 1)*512;
                const float* sw = swgt + (nxt & 1)*512;
                const int i0 = si[0*128+p], i1 = si[1*128+p];
                const int i2 = si[2*128+p], i3 = si[3*128+p];
                w0 = sw[0*128+p]; w1 = sw[1*128+p];
                w2 = sw[2*128+p]; w3 = sw[3*128+p];
                v0 = *(const float4*)(xb + (size_t)i0*CIN_ + co);
                v1 = *(const float4*)(xb + (size_t)i1*CIN_ + co);
                v2 = *(const float4*)(xb + (size_t)i2*CIN_ + co);
                v3 = *(const float4*)(xb + (size_t)i3*CIN_ + co);
            }

            // ---- MMA k-step ks (tensor pipe; hides the LDG latency) ----
            uint32_t bfr[4][4], ah[2][4], al[2][4];
#pragma unroll
            for (int np = 0; np < 4; np++)
                ldsm_x4(bfr[np], cur + FS_BH + bRow + np*2048 + boff);
#pragma unroll
            for (int mt = 0; mt < 2; mt++)
                ldsm_x4(ah[mt], cur + FS_AH + aRow + mt*2048 + aoff);
#pragma unroll
            for (int mt = 0; mt < 2; mt++)
#pragma unroll
                for (int nt = 0; nt < 8; nt++)
                    mma_bf16(acc[mt][nt], ah[mt],
                             bfr[nt >> 1][(nt & 1) * 2],
                             bfr[nt >> 1][(nt & 1) * 2 + 1]);
#pragma unroll
            for (int mt = 0; mt < 2; mt++)
                ldsm_x4(al[mt], cur + FS_AL + aRow + mt*2048 + aoff);
#pragma unroll
            for (int mt = 0; mt < 2; mt++)
#pragma unroll
                for (int nt = 0; nt < 8; nt++)
                    mma_bf16(acc[mt][nt], al[mt],
                             bfr[nt >> 1][(nt & 1) * 2],
                             bfr[nt >> 1][(nt & 1) * 2 + 1]);
#pragma unroll
            for (int np = 0; np < 4; np++)
                ldsm_x4(bfr[np], cur + FS_BL + bRow + np*2048 + boff);
#pragma unroll
            for (int mt = 0; mt < 2; mt++)
#pragma unroll
                for (int nt = 0; nt < 8; nt++)
                    mma_bf16(acc[mt][nt], ah[mt],
                             bfr[nt >> 1][(nt & 1) * 2],
                             bfr[nt >> 1][(nt & 1) * 2 + 1]);

            // ---- gather pass ks: combine + split + STS ----
            if (pre) {
                float r0 = fmaf(w3,v3.x, fmaf(w2,v2.x, fmaf(w1,v1.x, w0*v0.x)));
                float r1 = fmaf(w3,v3.y, fmaf(w2,v2.y, fmaf(w1,v1.y, w0*v0.y)));
                float r2 = fmaf(w3,v3.z, fmaf(w2,v2.z, fmaf(w1,v1.z, w0*v0.z)));
                float r3 = fmaf(w3,v3.w, fmaf(w2,v2.w, fmaf(w1,v1.w, w0*v0.w)));
                __nv_bfloat16 h0 = __float2bfloat16_rn(r0);
                __nv_bfloat16 h1 = __float2bfloat16_rn(r1);
                __nv_bfloat16 h2 = __float2bfloat16_rn(r2);
                __nv_bfloat16 h3 = __float2bfloat16_rn(r3);
                __nv_bfloat16 l0 = __float2bfloat16_rn(r0 - __bfloat162float(h0));
                __nv_bfloat16 l1 = __float2bfloat16_rn(r1 - __bfloat162float(h1));
                __nv_bfloat16 l2 = __float2bfloat16_rn(r2 - __bfloat162float(h2));
                __nv_bfloat16 l3 = __float2bfloat16_rn(r3 - __bfloat162float(h3));
                const uint32_t ao = (uint32_t)(p*128 + ((slot*8) ^ ((p & 7) << 4)));
                __nv_bfloat162 hA(h0, h1), hB(h2, h3), lA(l0, l1), lB(l2, l3);
                uint2 hv, lv;
                hv.x = *(uint32_t*)&hA; hv.y = *(uint32_t*)&hB;
                lv.x = *(uint32_t*)&lA; lv.y = *(uint32_t*)&lB;
                char* smc = sm + nxt_off;
                *(uint2*)(smc + FS_AH + ao) = hv;
                *(uint2*)(smc + FS_AL + ao) = lv;
            }
        }
    }

    // ---- epilogue: relu + store (NCHW) ----
    const size_t ob = (size_t)b * COUT_ * HW_ + hw0;
    const int mrow = wm*32 + (lane >> 2);
    const int ncol = wn*64 + (lane & 3) * 2;
#pragma unroll
    for (int mt = 0; mt < 2; mt++) {
#pragma unroll
        for (int nt = 0; nt < 8; nt++) {
            const int m = mrow + mt*16;
            const int n = ncol + nt*8;
            float* o0 = out + ob + (size_t)n * HW_ + m;
            o0[0]        = fmaxf(acc[mt][nt][0], 0.f);
            o0[HW_]      = fmaxf(acc[mt][nt][1], 0.f);
            o0[8]        = fmaxf(acc[mt][nt][2], 0.f);
            o0[HW_ + 8]  = fmaxf(acc[mt][nt][3], 0.f);
        }
    }
}

// ---------------------------------------------------------------------------
extern "C" void kernel_launch(void* const* d_in, const int* in_sizes, int n_in,
                              void* d_out, int out_size)
{
    (void)in_sizes; (void)n_in; (void)out_size;
    const float* x     = (const float*)d_in[0];
    const float* w_off = (const float*)d_in[1];
    const float* b_off = (const float*)d_in[2];
    const float* w_def = (const float*)d_in[3];
    float* out = (float*)d_out;

    float* xt;           cudaGetSymbolAddress((void**)&xt, g_xt);
    __nv_bfloat16* wbp;  cudaGetSymbolAddress((void**)&wbp, g_wb);

    transpose_kernel<<<dim3(HW_/32, CIN_/32, B_), dim3(32, 8)>>>(x, xt);
    prepack_kernel<<<NCHUNK, 256>>>(w_def, wbp);
    offset_kernel<<<B_*HW_/64, 256>>>(x, w_off, b_off);

    static bool attr_set = false;
    if (!attr_set) {
        cudaFuncSetAttribute(fused_kernel,
                             cudaFuncAttributeMaxDynamicSharedMemorySize, FSMEM);
        attr_set = true;
    }
    fused_kernel<<<NPB, 512, FSMEM>>>(xt, wbp, out);
}

// round 13
// speedup vs baseline: 1.0372x; 1.0162x over previous
#include <cuda_runtime.h>
#include <cuda_bf16.h>
#include <cstdint>

#define B_    2
#define CIN_  256
#define COUT_ 256
#define H_    128
#define W_    128
#define HW_   (H_*W_)
#define KK_   3
#define G_    4
#define OCH_  (G_*2*KK_*KK_)   // 72
#define KRED  (CIN_*KK_*KK_)   // 2304
#define NCHUNK (G_*KK_*KK_)    // 36 chunks of 64 k each
#define NPB   (B_*HW_/128)     // 256 pixel tiles

// Scratch buffers
__device__ float g_offset[B_*HW_*OCH_];                  // [pix][72]
__device__ float g_xt[(size_t)B_*HW_*CIN_];              // NHWC: [b][hw][c]
// weights: per (gt, couthalf): [hi 16KB | lo 16KB], SW128 swizzled [n][k]
__device__ __nv_bfloat16 g_wb[(size_t)NCHUNK*2*256*64];
// sampled A tiles: per (gt, pb): [hi 16KB | lo 16KB], SW128 swizzled [p][k]
__device__ __nv_bfloat16 g_a[(size_t)NCHUNK*NPB*128*64*2];

// ---------------------------------------------------------------------------
// helpers
// ---------------------------------------------------------------------------
__device__ __forceinline__ uint32_t smem_u32(const void* p) {
    uint32_t a;
    asm("{ .reg .u64 t; cvta.to.shared.u64 t, %1; cvt.u32.u64 %0, t; }" : "=r"(a) : "l"(p));
    return a;
}
__device__ __forceinline__ void ldsm_x4(uint32_t r[4], uint32_t addr) {
    asm volatile("ldmatrix.sync.aligned.m8n8.x4.shared.b16 {%0,%1,%2,%3}, [%4];"
                 : "=r"(r[0]), "=r"(r[1]), "=r"(r[2]), "=r"(r[3]) : "r"(addr));
}
__device__ __forceinline__ void mma_bf16(float d[4], const uint32_t a[4],
                                         uint32_t b0, uint32_t b1) {
    asm volatile(
        "mma.sync.aligned.m16n8k16.row.col.f32.bf16.bf16.f32 "
        "{%0,%1,%2,%3}, {%4,%5,%6,%7}, {%8,%9}, {%0,%1,%2,%3};"
        : "+f"(d[0]), "+f"(d[1]), "+f"(d[2]), "+f"(d[3])
        : "r"(a[0]), "r"(a[1]), "r"(a[2]), "r"(a[3]), "r"(b0), "r"(b1));
}
__device__ __forceinline__ void mbar_init(uint32_t mbar, uint32_t cnt) {
    asm volatile("mbarrier.init.shared.b64 [%0], %1;" :: "r"(mbar), "r"(cnt) : "memory");
}
__device__ __forceinline__ void mbar_expect_tx(uint32_t mbar, uint32_t bytes) {
    asm volatile("mbarrier.arrive.expect_tx.shared.b64 _, [%0], %1;"
                 :: "r"(mbar), "r"(bytes) : "memory");
}
__device__ __forceinline__ void mbar_wait(uint32_t mbar, uint32_t parity) {
    asm volatile(
        "{\n\t.reg .pred P;\n\t"
        "WL_%=:\n\t"
        "mbarrier.try_wait.parity.acquire.cta.shared::cta.b64 P, [%0], %1, 0x989680;\n\t"
        "@P bra.uni WD_%=;\n\t"
        "bra.uni WL_%=;\n\t"
        "WD_%=:\n\t}"
        :: "r"(mbar), "r"(parity) : "memory");
}
__device__ __forceinline__ void bulk_copy(uint32_t dst, const void* src, uint32_t bytes,
                                          uint32_t mbar) {
    asm volatile(
        "cp.async.bulk.shared::cta.global.mbarrier::complete_tx::bytes [%0], [%1], %2, [%3];"
        :: "r"(dst), "l"(src), "r"(bytes), "r"(mbar) : "memory");
}

// ---------------------------------------------------------------------------
// Kernel A: NCHW -> NHWC transpose (32x32 tiles)
// ---------------------------------------------------------------------------
__global__ void __launch_bounds__(256) transpose_kernel(const float* __restrict__ x,
                                                        float* __restrict__ xt)
{
    __shared__ float tl[32][33];
    const int tx = threadIdx.x, ty = threadIdx.y;
    const int bb = blockIdx.z;
    const int hw0 = blockIdx.x * 32;
    const int c0  = blockIdx.y * 32;
#pragma unroll
    for (int r = 0; r < 4; r++)
        tl[ty + 8*r][tx] = x[((size_t)bb*CIN_ + c0 + ty + 8*r)*HW_ + hw0 + tx];
    __syncthreads();
#pragma unroll
    for (int r = 0; r < 4; r++)
        xt[((size_t)bb*HW_ + hw0 + ty + 8*r)*CIN_ + c0 + tx] = tl[tx][ty + 8*r];
}

// ---------------------------------------------------------------------------
// Kernel B: weight prepack -> bf16 hi/lo, per (gt, couthalf) [hi 16K|lo 16K].
// ---------------------------------------------------------------------------
__global__ void __launch_bounds__(256) prepack_kernel(const float* __restrict__ wd,
                                                      __nv_bfloat16* __restrict__ wb)
{
    const int gt = blockIdx.x;
    const int g = gt / 9;
    const int tap = gt - 9*g;
    for (int idx = threadIdx.x; idx < 256*64; idx += 256) {
        const int n  = idx >> 6;
        const int cg = idx & 63;
        float v = wd[(size_t)n*KRED + (g*64 + cg)*9 + tap];
        __nv_bfloat16 h = __float2bfloat16_rn(v);
        __nv_bfloat16 l = __float2bfloat16_rn(v - __bfloat162float(h));
        const int ny = n >> 7;
        const int nl = n & 127;
        const size_t base = (size_t)gt*32768 + (size_t)ny*16384
                          + nl*64 + (cg ^ ((nl & 7) << 3));   // elems
        wb[base]        = h;      // hi
        wb[base + 8192] = l;      // lo (+16KB)
    }
}

// ---------------------------------------------------------------------------
// Kernel C: 1x1 offset conv (fp32)
// ---------------------------------------------------------------------------
__global__ void __launch_bounds__(256) offset_kernel(
    const float* __restrict__ x,
    const float* __restrict__ w,
    const float* __restrict__ bias)
{
    __shared__ float xs[16][64];
    __shared__ float ws[72][16];

    const int t    = threadIdx.x;
    const int pix0 = blockIdx.x * 64;
    const int b    = pix0 >> 14;
    const int rem  = pix0 & (HW_-1);
    const int hh   = rem >> 7;
    const int w0   = rem & (W_-1);

    const int p  = t & 63;
    const int oq = t >> 6;

    float acc[18];
#pragma unroll
    for (int i = 0; i < 18; i++) acc[i] = 0.f;

    const float* xbase = x + (size_t)b * CIN_ * HW_ + hh * W_ + w0;

    for (int c0 = 0; c0 < CIN_; c0 += 16) {
#pragma unroll
        for (int r = 0; r < 4; r++) {
            int e  = t + r * 256;
            int kk = e >> 6;
            int pp = e & 63;
            xs[kk][pp] = xbase[(size_t)(c0 + kk) * HW_ + pp];
        }
        for (int e = t; e < 72 * 16; e += 256) {
            int o  = e >> 4;
            int kk = e & 15;
            ws[o][kk] = w[o * CIN_ + c0 + kk];
        }
        __syncthreads();
#pragma unroll
        for (int kk = 0; kk < 16; kk++) {
            float xv = xs[kk][p];
#pragma unroll
            for (int i = 0; i < 18; i++)
                acc[i] = fmaf(xv, ws[oq * 18 + i][kk], acc[i]);
        }
        __syncthreads();
    }

    float* ob = g_offset + (size_t)(pix0 + p) * OCH_;
#pragma unroll
    for (int i = 0; i < 18; i++) {
        int o = oq * 18 + i;
        ob[o] = acc[i] + bias[o];
    }
}

// ---------------------------------------------------------------------------
// Kernel D: sampler — bilinear gather + bf16 hi/lo split, writes SW128
// swizzled [hi 16K | lo 16K] A-tiles to gmem. grid = (256, 36), 256 thr.
// ---------------------------------------------------------------------------
__global__ void __launch_bounds__(256) sample_kernel(const float* __restrict__ xt)
{
    __shared__ int   sidx[4*128];
    __shared__ float swgt[4*128];

    const int t  = threadIdx.x;
    const int pb = blockIdx.x;       // pixel tile
    const int gt = blockIdx.y;       // chunk
    const int pix0 = pb * 128;
    const int b    = pix0 >> 14;
    const int hw0  = pix0 & (HW_-1);
    const int hh   = hw0 >> 7;

    const int g   = gt / 9;
    const int tap = gt - 9*g;
    const int ti  = tap / 3;
    const int tj  = tap - 3*ti;
    const int gch = g * 64;

    if (t < 128) {
        const float* op = g_offset + (size_t)(pix0 + t) * OCH_ + gt*2;
        float ys = (float)(hh - 1 + ti) + op[0];
        float xs = (float)(t  - 1 + tj) + op[1];
        float y0f = floorf(ys), x0f = floorf(xs);
        int   y0  = (int)y0f,   x0  = (int)x0f;
        float ly = ys - y0f, lx = xs - x0f;
        float hy = 1.f - ly, hx = 1.f - lx;
        int y1 = y0 + 1, x1 = x0 + 1;
        bool vy0 = (unsigned)y0 < H_, vy1 = (unsigned)y1 < H_;
        bool vx0 = (unsigned)x0 < W_, vx1 = (unsigned)x1 < W_;
        int cy0 = min(max(y0,0),H_-1), cy1 = min(max(y1,0),H_-1);
        int cx0 = min(max(x0,0),W_-1), cx1 = min(max(x1,0),W_-1);
        sidx[0*128 + t] = cy0*W_ + cx0;
        sidx[1*128 + t] = cy0*W_ + cx1;
        sidx[2*128 + t] = cy1*W_ + cx0;
        sidx[3*128 + t] = cy1*W_ + cx1;
        swgt[0*128 + t] = (vy0 && vx0) ? hy*hx : 0.f;
        swgt[1*128 + t] = (vy0 && vx1) ? hy*lx : 0.f;
        swgt[2*128 + t] = (vy1 && vx0) ? ly*hx : 0.f;
        swgt[3*128 + t] = (vy1 && vx1) ? ly*lx : 0.f;
    }
    __syncthreads();

    const float* xb = xt + (size_t)b * HW_ * CIN_;
    const int slot = t & 15;
    const int gp   = t >> 4;

    char* outh = (char*)g_a + ((size_t)gt*NPB + pb) * 32768;
    char* outl = outh + 16384;

#pragma unroll
    for (int pass = 0; pass < 8; pass++) {
        const int p  = pass*16 + gp;
        const int i0 = sidx[0*128+p], i1 = sidx[1*128+p];
        const int i2 = sidx[2*128+p], i3 = sidx[3*128+p];
        const float w0 = swgt[0*128+p], w1 = swgt[1*128+p];
        const float w2 = swgt[2*128+p], w3 = swgt[3*128+p];
        const int co = gch + slot*4;
        float4 v0 = *(const float4*)(xb + (size_t)i0*CIN_ + co);
        float4 v1 = *(const float4*)(xb + (size_t)i1*CIN_ + co);
        float4 v2 = *(const float4*)(xb + (size_t)i2*CIN_ + co);
        float4 v3 = *(const float4*)(xb + (size_t)i3*CIN_ + co);
        float r0 = fmaf(w3,v3.x, fmaf(w2,v2.x, fmaf(w1,v1.x, w0*v0.x)));
        float r1 = fmaf(w3,v3.y, fmaf(w2,v2.y, fmaf(w1,v1.y, w0*v0.y)));
        float r2 = fmaf(w3,v3.z, fmaf(w2,v2.z, fmaf(w1,v1.z, w0*v0.z)));
        float r3 = fmaf(w3,v3.w, fmaf(w2,v2.w, fmaf(w1,v1.w, w0*v0.w)));

        __nv_bfloat16 h0 = __float2bfloat16_rn(r0);
        __nv_bfloat16 h1 = __float2bfloat16_rn(r1);
        __nv_bfloat16 h2 = __float2bfloat16_rn(r2);
        __nv_bfloat16 h3 = __float2bfloat16_rn(r3);
        __nv_bfloat16 l0 = __float2bfloat16_rn(r0 - __bfloat162float(h0));
        __nv_bfloat16 l1 = __float2bfloat16_rn(r1 - __bfloat162float(h1));
        __nv_bfloat16 l2 = __float2bfloat16_rn(r2 - __bfloat162float(h2));
        __nv_bfloat16 l3 = __float2bfloat16_rn(r3 - __bfloat162float(h3));

        const uint32_t off = (uint32_t)(p*128 + ((slot*8) ^ ((p & 7) << 4)));
        __nv_bfloat162 hA(h0, h1), hB(h2, h3), lA(l0, l1), lB(l2, l3);
        uint2 hv, lv;
        hv.x = *(uint32_t*)&hA; hv.y = *(uint32_t*)&hB;
        lv.x = *(uint32_t*)&lA; lv.y = *(uint32_t*)&lB;
        *(uint2*)(outh + off) = hv;
        *(uint2*)(outl + off) = lv;
    }
}

// ---------------------------------------------------------------------------
// Kernel E: GEMM on HMMA, 128 pix x 128 cout per block, 256 threads
// (8 warps = 4m x 2n, warp 32x64), 2 CTAs/SM. A double-buffered (32KB/stage,
// bulk copy), B single-buffered (32KB, bulk copy, L2-hot). R9 LDSM-reuse order.
// SMEM: Astage0 [0,32K) | Astage1 [32K,64K) | B [64K,96K) | mbars.
// ---------------------------------------------------------------------------
#define GS_B     65536
#define GS_MBARA 98304              // mbarA[0], mbarA[1]
#define GS_MBARB (GS_MBARA + 16)
#define GSMEM    (GS_MBARB + 8)     // 98328

__global__ void __launch_bounds__(256, 2)
gemm_kernel(const __nv_bfloat16* __restrict__ wb, float* __restrict__ out)
{
    extern __shared__ char sm[];
    const uint32_t sb = smem_u32(sm);

    const int t = threadIdx.x;
    const int warp = t >> 5, lane = t & 31;
    const int pb   = blockIdx.x;
    const int ny   = blockIdx.y;          // cout half
    const int pix0 = pb * 128;
    const int b    = pix0 >> 14;
    const int hw0  = pix0 & (HW_-1);

    if (t == 0) {
        mbar_init(sb + GS_MBARA, 1);
        mbar_init(sb + GS_MBARA + 8, 1);
        mbar_init(sb + GS_MBARB, 1);
    }
    __syncthreads();

    const int wm = warp & 3, wn = warp >> 2;

    const uint32_t rowA = wm*32 + (lane & 15);
    const uint32_t swzA = (rowA & 7) << 4;
    const uint32_t kA   = (uint32_t)(lane & 16);
    const uint32_t aRow = rowA * 128;

    const uint32_t rowB = wn*64 + (lane & 7) + ((lane & 16) >> 1);
    const uint32_t swzB = (rowB & 7) << 4;
    const uint32_t kB   = (uint32_t)((lane & 8) << 1);
    const uint32_t bRow = rowB * 128;

    const char* asrc = (const char*)g_a + (size_t)pb * 32768;   // + gt*NPB*32768
    const char* bsrc = (const char*)wb + (size_t)ny * 32768;    // + gt*65536

    float acc[2][8][4];
#pragma unroll
    for (int i = 0; i < 2; i++)
#pragma unroll
        for (int j = 0; j < 8; j++)
#pragma unroll
            for (int q = 0; q < 4; q++) acc[i][j][q] = 0.f;

    // prologue: A(0) -> stage 0
    if (t == 0) {
        mbar_expect_tx(sb + GS_MBARA, 32768);
        bulk_copy(sb, asrc, 32768, sb + GS_MBARA);
    }

    for (int gt = 0; gt < NCHUNK; gt++) {
        const int s = gt & 1;
        const uint32_t curA = sb + s * 32768;

        __syncthreads();   // all warps done with MMA(gt-1): A stage s^1 + B free

        if (t == 0) {
            if (gt + 1 < NCHUNK) {
                uint32_t mbA = sb + GS_MBARA + ((gt + 1) & 1) * 8;
                mbar_expect_tx(mbA, 32768);
                bulk_copy(sb + ((gt + 1) & 1) * 32768,
                          asrc + (size_t)(gt + 1) * NPB * 32768, 32768, mbA);
            }
            mbar_expect_tx(sb + GS_MBARB, 32768);
            bulk_copy(sb + GS_B, bsrc + (size_t)gt * 65536, 32768, sb + GS_MBARB);
        }

        mbar_wait(sb + GS_MBARA + s * 8, (gt >> 1) & 1);
        mbar_wait(sb + GS_MBARB, gt & 1);

        // 4 k-steps; fragment-reuse order: hi*hi -> lo*hi -> hi*lo
#pragma unroll
        for (int ks = 0; ks < 4; ks++) {
            const uint32_t kbyte = (uint32_t)(ks * 32);
            const uint32_t aoff = (kbyte + kA) ^ swzA;
            const uint32_t boff = (kbyte + kB) ^ swzB;

            uint32_t bfr[4][4], ah[2][4], al[2][4];

#pragma unroll
            for (int np = 0; np < 4; np++)
                ldsm_x4(bfr[np], sb + GS_B + bRow + np*2048 + boff);
#pragma unroll
            for (int mt = 0; mt < 2; mt++)
                ldsm_x4(ah[mt], curA + aRow + mt*2048 + aoff);

#pragma unroll
            for (int mt = 0; mt < 2; mt++)
#pragma unroll
                for (int nt = 0; nt < 8; nt++)
                    mma_bf16(acc[mt][nt], ah[mt],
                             bfr[nt >> 1][(nt & 1) * 2],
                             bfr[nt >> 1][(nt & 1) * 2 + 1]);

#pragma unroll
            for (int mt = 0; mt < 2; mt++)
                ldsm_x4(al[mt], curA + 16384 + aRow + mt*2048 + aoff);
#pragma unroll
            for (int mt = 0; mt < 2; mt++)
#pragma unroll
                for (int nt = 0; nt < 8; nt++)
                    mma_bf16(acc[mt][nt], al[mt],
                             bfr[nt >> 1][(nt & 1) * 2],
                             bfr[nt >> 1][(nt & 1) * 2 + 1]);

#pragma unroll
            for (int np = 0; np < 4; np++)
                ldsm_x4(bfr[np], sb + GS_B + 16384 + bRow + np*2048 + boff);
#pragma unroll
            for (int mt = 0; mt < 2; mt++)
#pragma unroll
                for (int nt = 0; nt < 8; nt++)
                    mma_bf16(acc[mt][nt], ah[mt],
                             bfr[nt >> 1][(nt & 1) * 2],
                             bfr[nt >> 1][(nt & 1) * 2 + 1]);
        }
    }

    // ---- epilogue: relu + store (NCHW) ----
    const size_t ob = (size_t)b * COUT_ * HW_ + hw0;
    const int mrow = wm*32 + (lane >> 2);
    const int ncol = ny*128 + wn*64 + (lane & 3) * 2;
#pragma unroll
    for (int mt = 0; mt < 2; mt++) {
#pragma unroll
        for (int nt = 0; nt < 8; nt++) {
            const int m = mrow + mt*16;
            const int n = ncol + nt*8;
            float* o0 = out + ob + (size_t)n * HW_ + m;
            o0[0]        = fmaxf(acc[mt][nt][0], 0.f);
            o0[HW_]      = fmaxf(acc[mt][nt][1], 0.f);
            o0[8]        = fmaxf(acc[mt][nt][2], 0.f);
            o0[HW_ + 8]  = fmaxf(acc[mt][nt][3], 0.f);
        }
    }
}

// ---------------------------------------------------------------------------
extern "C" void kernel_launch(void* const* d_in, const int* in_sizes, int n_in,
                              void* d_out, int out_size)
{
    (void)in_sizes; (void)n_in; (void)out_size;
    const float* x     = (const float*)d_in[0];
    const float* w_off = (const float*)d_in[1];
    const float* b_off = (const float*)d_in[2];
    const float* w_def = (const float*)d_in[3];
    float* out = (float*)d_out;

    float* xt;           cudaGetSymbolAddress((void**)&xt, g_xt);
    __nv_bfloat16* wbp;  cudaGetSymbolAddress((void**)&wbp, g_wb);

    transpose_kernel<<<dim3(HW_/32, CIN_/32, B_), dim3(32, 8)>>>(x, xt);
    prepack_kernel<<<NCHUNK, 256>>>(w_def, wbp);
    offset_kernel<<<B_*HW_/64, 256>>>(x, w_off, b_off);
    sample_kernel<<<dim3(NPB, NCHUNK), 256>>>(xt);

    static bool attr_set = false;
    if (!attr_set) {
        cudaFuncSetAttribute(gemm_kernel,
                             cudaFuncAttributeMaxDynamicSharedMemorySize, GSMEM);
        attr_set = true;
    }
    gemm_kernel<<<dim3(NPB, 2), 256, GSMEM>>>(wbp, out);
}

// round 14
// speedup vs baseline: 1.0633x; 1.0252x over previous
#include <cuda_runtime.h>
#include <cuda_bf16.h>
#include <cstdint>

#define B_    2
#define CIN_  256
#define COUT_ 256
#define H_    128
#define W_    128
#define HW_   (H_*W_)
#define KK_   3
#define G_    4
#define OCH_  (G_*2*KK_*KK_)   // 72
#define KRED  (CIN_*KK_*KK_)   // 2304
#define NCHUNK (G_*KK_*KK_)    // 36 chunks of 64 k each
#define NPB   (B_*HW_/128)     // 256 pixel tiles

// Scratch buffers
__device__ float g_offset[B_*HW_*OCH_];                  // [pix][72]
__device__ float g_xt[(size_t)B_*HW_*CIN_];              // NHWC: [b][hw][c]
__device__ __nv_bfloat16 g_wb[(size_t)NCHUNK*2*256*64];  // per chunk: [hi 32KB][lo 32KB] swizzled [n][k]
// Sampled A tiles, SW128-swizzled, 16KB per (chunk, pixtile)
__device__ __nv_bfloat16 g_ah[(size_t)NCHUNK*NPB*128*64];
__device__ __nv_bfloat16 g_al[(size_t)NCHUNK*NPB*128*64];

// ---------------------------------------------------------------------------
// helpers
// ---------------------------------------------------------------------------
__device__ __forceinline__ uint32_t smem_u32(const void* p) {
    uint32_t a;
    asm("{ .reg .u64 t; cvta.to.shared.u64 t, %1; cvt.u32.u64 %0, t; }" : "=r"(a) : "l"(p));
    return a;
}
__device__ __forceinline__ void ldsm_x4(uint32_t r[4], uint32_t addr) {
    asm volatile("ldmatrix.sync.aligned.m8n8.x4.shared.b16 {%0,%1,%2,%3}, [%4];"
                 : "=r"(r[0]), "=r"(r[1]), "=r"(r[2]), "=r"(r[3]) : "r"(addr));
}
__device__ __forceinline__ void mma_bf16(float d[4], const uint32_t a[4],
                                         uint32_t b0, uint32_t b1) {
    asm volatile(
        "mma.sync.aligned.m16n8k16.row.col.f32.bf16.bf16.f32 "
        "{%0,%1,%2,%3}, {%4,%5,%6,%7}, {%8,%9}, {%0,%1,%2,%3};"
        : "+f"(d[0]), "+f"(d[1]), "+f"(d[2]), "+f"(d[3])
        : "r"(a[0]), "r"(a[1]), "r"(a[2]), "r"(a[3]), "r"(b0), "r"(b1));
}
__device__ __forceinline__ void mbar_init(uint32_t mbar, uint32_t cnt) {
    asm volatile("mbarrier.init.shared.b64 [%0], %1;" :: "r"(mbar), "r"(cnt) : "memory");
}
__device__ __forceinline__ void mbar_expect_tx(uint32_t mbar, uint32_t bytes) {
    asm volatile("mbarrier.arrive.expect_tx.shared.b64 _, [%0], %1;"
                 :: "r"(mbar), "r"(bytes) : "memory");
}
__device__ __forceinline__ void mbar_wait(uint32_t mbar, uint32_t parity) {
    asm volatile(
        "{\n\t.reg .pred P;\n\t"
        "WL_%=:\n\t"
        "mbarrier.try_wait.parity.acquire.cta.shared::cta.b64 P, [%0], %1, 0x989680;\n\t"
        "@P bra.uni WD_%=;\n\t"
        "bra.uni WL_%=;\n\t"
        "WD_%=:\n\t}"
        :: "r"(mbar), "r"(parity) : "memory");
}
__device__ __forceinline__ void bulk_copy(uint32_t dst, const void* src, uint32_t bytes,
                                          uint32_t mbar) {
    asm volatile(
        "cp.async.bulk.shared::cta.global.mbarrier::complete_tx::bytes [%0], [%1], %2, [%3];"
        :: "r"(dst), "l"(src), "r"(bytes), "r"(mbar) : "memory");
}

// ---------------------------------------------------------------------------
// Kernel A (merged): NCHW->NHWC transpose + 1x1 offset conv.
// One 64-pixel block stages x in SMEM once, emits both outputs.
// ---------------------------------------------------------------------------
__global__ void __launch_bounds__(256) prep_kernel(
    const float* __restrict__ x,
    const float* __restrict__ w,
    const float* __restrict__ bias,
    float* __restrict__ xt)
{
    __shared__ float xs[128][65];   // half of channels x 64 pixels (padded)
    __shared__ float wss[72][16];

    const int t    = threadIdx.x;
    const int pix0 = blockIdx.x * 64;
    const int b    = pix0 >> 14;
    const int hw0  = pix0 & (HW_-1);

    const int p  = t & 63;
    const int oq = t >> 6;

    float acc[18];
#pragma unroll
    for (int i = 0; i < 18; i++) acc[i] = 0.f;

    const float* xb = x + (size_t)b * CIN_ * HW_ + hw0;

    for (int c0 = 0; c0 < CIN_; c0 += 128) {
        __syncthreads();   // xs free (prev half's reads done)

        // stage 128 channels x 64 pixels
        for (int e = t; e < 128 * 64; e += 256) {
            int kk = e >> 6;
            int pp = e & 63;
            xs[kk][pp] = xb[(size_t)(c0 + kk) * HW_ + pp];
        }
        __syncthreads();

        // transpose write: xt[pix][c], coalesced in c
        for (int e = t; e < 64 * 128; e += 256) {
            int pp = e >> 7;
            int c  = e & 127;
            xt[(size_t)(pix0 + pp) * CIN_ + c0 + c] = xs[c][pp];
        }

        // offset conv accumulation in 16-channel slices
        for (int s16 = 0; s16 < 128; s16 += 16) {
            __syncthreads();   // wss free
            for (int e = t; e < 72 * 16; e += 256) {
                int o  = e >> 4;
                int kk = e & 15;
                wss[o][kk] = w[o * CIN_ + c0 + s16 + kk];
            }
            __syncthreads();
#pragma unroll
            for (int kk = 0; kk < 16; kk++) {
                float xv = xs[s16 + kk][p];
#pragma unroll
                for (int i = 0; i < 18; i++)
                    acc[i] = fmaf(xv, wss[oq * 18 + i][kk], acc[i]);
            }
        }
    }

    float* ob = g_offset + (size_t)(pix0 + p) * OCH_;
#pragma unroll
    for (int i = 0; i < 18; i++) {
        int o = oq * 18 + i;
        ob[o] = acc[i] + bias[o];
    }
}

// ---------------------------------------------------------------------------
// Kernel B: weight prepack -> bf16 hi/lo, [n][k] tiles, SW128 swizzled.
// ---------------------------------------------------------------------------
__global__ void __launch_bounds__(256) prepack_kernel(const float* __restrict__ wd,
                                                      __nv_bfloat16* __restrict__ wb)
{
    const int gt = blockIdx.x;
    const int g = gt / 9;
    const int tap = gt - 9*g;
    for (int idx = threadIdx.x; idx < 256*64; idx += 256) {
        const int n  = idx >> 6;
        const int cg = idx & 63;
        float v = wd[(size_t)n*KRED + (g*64 + cg)*9 + tap];
        __nv_bfloat16 h = __float2bfloat16_rn(v);
        __nv_bfloat16 l = __float2bfloat16_rn(v - __bfloat162float(h));
        const int dst = n*64 + (cg ^ ((n & 7) << 3));   // SW128 (bf16 elems)
        wb[(size_t)gt*32768 + dst]          = h;
        wb[(size_t)gt*32768 + 16384 + dst]  = l;
    }
}

// ---------------------------------------------------------------------------
// Kernel C: sampler — bilinear gather + bf16 hi/lo split, SW128-swizzled
// A-tiles to gmem. Each thread handles 8 channels -> STG.128 stores.
// grid = (256 pixtiles, 36 chunks), 256 threads.
// ---------------------------------------------------------------------------
__global__ void __launch_bounds__(256) sample_kernel(const float* __restrict__ xt)
{
    __shared__ int   sidx[4*128];
    __shared__ float swgt[4*128];

    const int t  = threadIdx.x;
    const int pb = blockIdx.x;
    const int gt = blockIdx.y;
    const int pix0 = pb * 128;
    const int b    = pix0 >> 14;
    const int hw0  = pix0 & (HW_-1);
    const int hh   = hw0 >> 7;

    const int g   = gt / 9;
    const int tap = gt - 9*g;
    const int ti  = tap / 3;
    const int tj  = tap - 3*ti;
    const int gch = g * 64;

    if (t < 128) {
        const float* op = g_offset + (size_t)(pix0 + t) * OCH_ + gt*2;
        float ys = (float)(hh - 1 + ti) + op[0];
        float xs = (float)(t  - 1 + tj) + op[1];
        float y0f = floorf(ys), x0f = floorf(xs);
        int   y0  = (int)y0f,   x0  = (int)x0f;
        float ly = ys - y0f, lx = xs - x0f;
        float hy = 1.f - ly, hx = 1.f - lx;
        int y1 = y0 + 1, x1 = x0 + 1;
        bool vy0 = (unsigned)y0 < H_, vy1 = (unsigned)y1 < H_;
        bool vx0 = (unsigned)x0 < W_, vx1 = (unsigned)x1 < W_;
        int cy0 = min(max(y0,0),H_-1), cy1 = min(max(y1,0),H_-1);
        int cx0 = min(max(x0,0),W_-1), cx1 = min(max(x1,0),W_-1);
        sidx[0*128 + t] = cy0*W_ + cx0;
        sidx[1*128 + t] = cy0*W_ + cx1;
        sidx[2*128 + t] = cy1*W_ + cx0;
        sidx[3*128 + t] = cy1*W_ + cx1;
        swgt[0*128 + t] = (vy0 && vx0) ? hy*hx : 0.f;
        swgt[1*128 + t] = (vy0 && vx1) ? hy*lx : 0.f;
        swgt[2*128 + t] = (vy1 && vx0) ? ly*hx : 0.f;
        swgt[3*128 + t] = (vy1 && vx1) ? ly*lx : 0.f;
    }
    __syncthreads();

    const float* xb = xt + (size_t)b * HW_ * CIN_;
    const int slot = t & 7;          // 8-channel slot
    const int gp   = t >> 3;         // 0..31

    char* outh = (char*)g_ah + ((size_t)gt*NPB + pb) * 16384;
    char* outl = (char*)g_al + ((size_t)gt*NPB + pb) * 16384;

#pragma unroll
    for (int pass = 0; pass < 4; pass++) {
        const int p  = pass*32 + gp;
        const int i0 = sidx[0*128+p], i1 = sidx[1*128+p];
        const int i2 = sidx[2*128+p], i3 = sidx[3*128+p];
        const float w0 = swgt[0*128+p], w1 = swgt[1*128+p];
        const float w2 = swgt[2*128+p], w3 = swgt[3*128+p];
        const int co = gch + slot*8;

        float4 a0 = *(const float4*)(xb + (size_t)i0*CIN_ + co);
        float4 b0 = *(const float4*)(xb + (size_t)i0*CIN_ + co + 4);
        float4 a1 = *(const float4*)(xb + (size_t)i1*CIN_ + co);
        float4 b1 = *(const float4*)(xb + (size_t)i1*CIN_ + co + 4);
        float4 a2 = *(const float4*)(xb + (size_t)i2*CIN_ + co);
        float4 b2 = *(const float4*)(xb + (size_t)i2*CIN_ + co + 4);
        float4 a3 = *(const float4*)(xb + (size_t)i3*CIN_ + co);
        float4 b3 = *(const float4*)(xb + (size_t)i3*CIN_ + co + 4);

        float r[8];
        r[0] = fmaf(w3,a3.x, fmaf(w2,a2.x, fmaf(w1,a1.x, w0*a0.x)));
        r[1] = fmaf(w3,a3.y, fmaf(w2,a2.y, fmaf(w1,a1.y, w0*a0.y)));
        r[2] = fmaf(w3,a3.z, fmaf(w2,a2.z, fmaf(w1,a1.z, w0*a0.z)));
        r[3] = fmaf(w3,a3.w, fmaf(w2,a2.w, fmaf(w1,a1.w, w0*a0.w)));
        r[4] = fmaf(w3,b3.x, fmaf(w2,b2.x, fmaf(w1,b1.x, w0*b0.x)));
        r[5] = fmaf(w3,b3.y, fmaf(w2,b2.y, fmaf(w1,b1.y, w0*b0.y)));
        r[6] = fmaf(w3,b3.z, fmaf(w2,b2.z, fmaf(w1,b1.z, w0*b0.z)));
        r[7] = fmaf(w3,b3.w, fmaf(w2,b2.w, fmaf(w1,b1.w, w0*b0.w)));

        uint32_t hw4[4], lw4[4];
#pragma unroll
        for (int q = 0; q < 4; q++) {
            __nv_bfloat16 hA = __float2bfloat16_rn(r[2*q]);
            __nv_bfloat16 hB = __float2bfloat16_rn(r[2*q+1]);
            __nv_bfloat16 lA = __float2bfloat16_rn(r[2*q]   - __bfloat162float(hA));
            __nv_bfloat16 lB = __float2bfloat16_rn(r[2*q+1] - __bfloat162float(hB));
            __nv_bfloat162 hp(hA, hB), lp(lA, lB);
            hw4[q] = *(uint32_t*)&hp;
            lw4[q] = *(uint32_t*)&lp;
        }

        const uint32_t aoff = (uint32_t)(p*128 + ((slot*16) ^ ((p & 7) << 4)));
        *(uint4*)(outh + aoff) = make_uint4(hw4[0], hw4[1], hw4[2], hw4[3]);
        *(uint4*)(outl + aoff) = make_uint4(lw4[0], lw4[1], lw4[2], lw4[3]);
    }
}

// ---------------------------------------------------------------------------
// Kernel D: pure GEMM on HMMA (exact R9 config: 475.8us best).
// 128 pix x 256 cout, 512 threads (16 warps = 4m x 4n, warp 32x64).
// 2-stage bulk-copy pipeline; LDSM fragment-reuse order (12 LDSM/k-step).
// Stage = Ah 16K | Al 16K | Bh 32K | Bl 32K = 96KB.
// ---------------------------------------------------------------------------
#define GS_AH 0
#define GS_AL 16384
#define GS_BH 32768
#define GS_BL 65536
#define GSTAGE 98304
#define GS_MBAR (2*GSTAGE)
#define GSMEM (2*GSTAGE + 32)

__device__ __forceinline__ void gemm_issue_bulk(uint32_t sbase, uint32_t mbar,
                                                int gt, int pb,
                                                const __nv_bfloat16* wb)
{
    const char* ah = (const char*)g_ah + ((size_t)gt*NPB + pb) * 16384;
    const char* al = (const char*)g_al + ((size_t)gt*NPB + pb) * 16384;
    const char* bs = (const char*)wb + (size_t)gt * 65536;
    mbar_expect_tx(mbar, GSTAGE);
    bulk_copy(sbase + GS_AH, ah, 16384, mbar);
    bulk_copy(sbase + GS_AL, al, 16384, mbar);
    bulk_copy(sbase + GS_BH, bs, 65536, mbar);
}

__global__ void __launch_bounds__(512, 1)
gemm_kernel(const __nv_bfloat16* __restrict__ wb, float* __restrict__ out)
{
    extern __shared__ char sm[];
    const uint32_t sb = smem_u32(sm);

    const int t = threadIdx.x;
    const int warp = t >> 5, lane = t & 31;
    const int pb   = blockIdx.x;
    const int pix0 = pb * 128;
    const int b    = pix0 >> 14;
    const int hw0  = pix0 & (HW_-1);

    if (t == 0) {
        mbar_init(sb + GS_MBAR, 1);
        mbar_init(sb + GS_MBAR + 8, 1);
    }
    __syncthreads();

    const int wm = warp & 3, wn = warp >> 2;

    const uint32_t rowA = wm*32 + (lane & 15);
    const uint32_t swzA = (rowA & 7) << 4;
    const uint32_t kA   = (uint32_t)(lane & 16);
    const uint32_t aRow = rowA * 128;

    const uint32_t rowB = wn*64 + (lane & 7) + ((lane & 16) >> 1);
    const uint32_t swzB = (rowB & 7) << 4;
    const uint32_t kB   = (uint32_t)((lane & 8) << 1);
    const uint32_t bRow = rowB * 128;

    float acc[2][8][4];
#pragma unroll
    for (int i = 0; i < 2; i++)
#pragma unroll
        for (int j = 0; j < 8; j++)
#pragma unroll
            for (int q = 0; q < 4; q++) acc[i][j][q] = 0.f;

    if (t == 0) gemm_issue_bulk(sb, sb + GS_MBAR, 0, pb, wb);

    for (int gt = 0; gt < NCHUNK; gt++) {
        const int s = gt & 1;
        const uint32_t cur = sb + s * GSTAGE;
        if (gt + 1 < NCHUNK && t == 0)
            gemm_issue_bulk(sb + ((gt + 1) & 1) * GSTAGE,
                            sb + GS_MBAR + ((gt + 1) & 1) * 8, gt + 1, pb, wb);

        mbar_wait(sb + GS_MBAR + s * 8, (gt >> 1) & 1);

#pragma unroll
        for (int ks = 0; ks < 4; ks++) {
            const uint32_t kbyte = (uint32_t)(ks * 32);
            const uint32_t aoff = (kbyte + kA) ^ swzA;
            const uint32_t boff = (kbyte + kB) ^ swzB;

            uint32_t bfr[4][4], ah[2][4], al[2][4];

#pragma unroll
            for (int np = 0; np < 4; np++)
                ldsm_x4(bfr[np], cur + GS_BH + bRow + np*2048 + boff);
#pragma unroll
            for (int mt = 0; mt < 2; mt++)
                ldsm_x4(ah[mt], cur + GS_AH + aRow + mt*2048 + aoff);

#pragma unroll
            for (int mt = 0; mt < 2; mt++)
#pragma unroll
                for (int nt = 0; nt < 8; nt++)
                    mma_bf16(acc[mt][nt], ah[mt],
                             bfr[nt >> 1][(nt & 1) * 2],
                             bfr[nt >> 1][(nt & 1) * 2 + 1]);

#pragma unroll
            for (int mt = 0; mt < 2; mt++)
                ldsm_x4(al[mt], cur + GS_AL + aRow + mt*2048 + aoff);
#pragma unroll
            for (int mt = 0; mt < 2; mt++)
#pragma unroll
                for (int nt = 0; nt < 8; nt++)
                    mma_bf16(acc[mt][nt], al[mt],
                             bfr[nt >> 1][(nt & 1) * 2],
                             bfr[nt >> 1][(nt & 1) * 2 + 1]);

#pragma unroll
            for (int np = 0; np < 4; np++)
                ldsm_x4(bfr[np], cur + GS_BL + bRow + np*2048 + boff);
#pragma unroll
            for (int mt = 0; mt < 2; mt++)
#pragma unroll
                for (int nt = 0; nt < 8; nt++)
                    mma_bf16(acc[mt][nt], ah[mt],
                             bfr[nt >> 1][(nt & 1) * 2],
                             bfr[nt >> 1][(nt & 1) * 2 + 1]);
        }
        __syncthreads();
    }

    // epilogue: relu + store (NCHW)
    const size_t ob = (size_t)b * COUT_ * HW_ + hw0;
    const int mrow = wm*32 + (lane >> 2);
    const int ncol = wn*64 + (lane & 3) * 2;
#pragma unroll
    for (int mt = 0; mt < 2; mt++) {
#pragma unroll
        for (int nt = 0; nt < 8; nt++) {
            const int m = mrow + mt*16;
            const int n = ncol + nt*8;
            float* o0 = out + ob + (size_t)n * HW_ + m;
            o0[0]        = fmaxf(acc[mt][nt][0], 0.f);
            o0[HW_]      = fmaxf(acc[mt][nt][1], 0.f);
            o0[8]        = fmaxf(acc[mt][nt][2], 0.f);
            o0[HW_ + 8]  = fmaxf(acc[mt][nt][3], 0.f);
        }
    }
}

// ---------------------------------------------------------------------------
extern "C" void kernel_launch(void* const* d_in, const int* in_sizes, int n_in,
                              void* d_out, int out_size)
{
    (void)in_sizes; (void)n_in; (void)out_size;
    const float* x     = (const float*)d_in[0];
    const float* w_off = (const float*)d_in[1];
    const float* b_off = (const float*)d_in[2];
    const float* w_def = (const float*)d_in[3];
    float* out = (float*)d_out;

    float* xt;           cudaGetSymbolAddress((void**)&xt, g_xt);
    __nv_bfloat16* wbp;  cudaGetSymbolAddress((void**)&wbp, g_wb);

    prep_kernel<<<B_*HW_/64, 256>>>(x, w_off, b_off, xt);
    prepack_kernel<<<NCHUNK, 256>>>(w_def, wbp);
    sample_kernel<<<dim3(NPB, NCHUNK), 256>>>(xt);

    static bool attr_set = false;
    if (!attr_set) {
        cudaFuncSetAttribute(gemm_kernel,
                             cudaFuncAttributeMaxDynamicSharedMemorySize, GSMEM);
        attr_set = true;
    }
    gemm_kernel<<<NPB, 512, GSMEM>>>(wbp, out);
}

// round 15
// speedup vs baseline: 1.1556x; 1.0868x over previous
#include <cuda_runtime.h>
#include <cuda_bf16.h>
#include <cstdint>

#define B_    2
#define CIN_  256
#define COUT_ 256
#define H_    128
#define W_    128
#define HW_   (H_*W_)
#define KK_   3
#define G_    4
#define OCH_  (G_*2*KK_*KK_)   // 72
#define KRED  (CIN_*KK_*KK_)   // 2304
#define NCHUNK (G_*KK_*KK_)    // 36 chunks of 64 k each
#define NPB   (B_*HW_/128)     // 256 pixel tiles
#define QPB   (NPB/4)          // 64 pixel tiles per quarter

// Scratch buffers
__device__ float g_offset[B_*HW_*OCH_];                  // [pix][72]
__device__ float g_xt[(size_t)B_*HW_*CIN_];              // NHWC: [b][hw][c]
__device__ __nv_bfloat16 g_wb[(size_t)NCHUNK*2*256*64];  // per chunk: [hi 32KB][lo 32KB] swizzled [n][k]
__device__ __nv_bfloat16 g_ah[(size_t)NCHUNK*NPB*128*64];
__device__ __nv_bfloat16 g_al[(size_t)NCHUNK*NPB*128*64];

// ---------------------------------------------------------------------------
// helpers
// ---------------------------------------------------------------------------
__device__ __forceinline__ uint32_t smem_u32(const void* p) {
    uint32_t a;
    asm("{ .reg .u64 t; cvta.to.shared.u64 t, %1; cvt.u32.u64 %0, t; }" : "=r"(a) : "l"(p));
    return a;
}
__device__ __forceinline__ void ldsm_x4(uint32_t r[4], uint32_t addr) {
    asm volatile("ldmatrix.sync.aligned.m8n8.x4.shared.b16 {%0,%1,%2,%3}, [%4];"
                 : "=r"(r[0]), "=r"(r[1]), "=r"(r[2]), "=r"(r[3]) : "r"(addr));
}
__device__ __forceinline__ void mma_bf16(float d[4], const uint32_t a[4],
                                         uint32_t b0, uint32_t b1) {
    asm volatile(
        "mma.sync.aligned.m16n8k16.row.col.f32.bf16.bf16.f32 "
        "{%0,%1,%2,%3}, {%4,%5,%6,%7}, {%8,%9}, {%0,%1,%2,%3};"
        : "+f"(d[0]), "+f"(d[1]), "+f"(d[2]), "+f"(d[3])
        : "r"(a[0]), "r"(a[1]), "r"(a[2]), "r"(a[3]), "r"(b0), "r"(b1));
}
__device__ __forceinline__ void mbar_init(uint32_t mbar, uint32_t cnt) {
    asm volatile("mbarrier.init.shared.b64 [%0], %1;" :: "r"(mbar), "r"(cnt) : "memory");
}
__device__ __forceinline__ void mbar_expect_tx(uint32_t mbar, uint32_t bytes) {
    asm volatile("mbarrier.arrive.expect_tx.shared.b64 _, [%0], %1;"
                 :: "r"(mbar), "r"(bytes) : "memory");
}
__device__ __forceinline__ void mbar_wait(uint32_t mbar, uint32_t parity) {
    asm volatile(
        "{\n\t.reg .pred P;\n\t"
        "WL_%=:\n\t"
        "mbarrier.try_wait.parity.acquire.cta.shared::cta.b64 P, [%0], %1, 0x989680;\n\t"
        "@P bra.uni WD_%=;\n\t"
        "bra.uni WL_%=;\n\t"
        "WD_%=:\n\t}"
        :: "r"(mbar), "r"(parity) : "memory");
}
__device__ __forceinline__ void bulk_copy(uint32_t dst, const void* src, uint32_t bytes,
                                          uint32_t mbar) {
    asm volatile(
        "cp.async.bulk.shared::cta.global.mbarrier::complete_tx::bytes [%0], [%1], %2, [%3];"
        :: "r"(dst), "l"(src), "r"(bytes), "r"(mbar) : "memory");
}

// ---------------------------------------------------------------------------
// Kernel A: quarter transpose NCHW -> NHWC (32x32 tiles). pbbase selects the
// 8192-pixel quarter (all within one image).
// ---------------------------------------------------------------------------
__global__ void __launch_bounds__(256) transpose_q(const float* __restrict__ x,
                                                   float* __restrict__ xt,
                                                   int pbbase)
{
    __shared__ float tl[32][33];
    const int tx = threadIdx.x, ty = threadIdx.y;
    const int bb    = pbbase >> 7;
    const int hwqb  = (pbbase * 128) & (HW_-1);
    const int hw0 = hwqb + blockIdx.x * 32;
    const int c0  = blockIdx.y * 32;
#pragma unroll
    for (int r = 0; r < 4; r++)
        tl[ty + 8*r][tx] = x[((size_t)bb*CIN_ + c0 + ty + 8*r)*HW_ + hw0 + tx];
    __syncthreads();
#pragma unroll
    for (int r = 0; r < 4; r++)
        xt[((size_t)bb*HW_ + hw0 + ty + 8*r)*CIN_ + c0 + tx] = tl[tx][ty + 8*r];
}

// ---------------------------------------------------------------------------
// Kernel B: weight prepack -> bf16 hi/lo, [n][k] tiles, SW128 swizzled.
// ---------------------------------------------------------------------------
__global__ void __launch_bounds__(256) prepack_kernel(const float* __restrict__ wd,
                                                      __nv_bfloat16* __restrict__ wb)
{
    const int gt = blockIdx.x;
    const int g = gt / 9;
    const int tap = gt - 9*g;
    for (int idx = threadIdx.x; idx < 256*64; idx += 256) {
        const int n  = idx >> 6;
        const int cg = idx & 63;
        float v = wd[(size_t)n*KRED + (g*64 + cg)*9 + tap];
        __nv_bfloat16 h = __float2bfloat16_rn(v);
        __nv_bfloat16 l = __float2bfloat16_rn(v - __bfloat162float(h));
        const int dst = n*64 + (cg ^ ((n & 7) << 3));   // SW128 (bf16 elems)
        wb[(size_t)gt*32768 + dst]          = h;
        wb[(size_t)gt*32768 + 16384 + dst]  = l;
    }
}

// ---------------------------------------------------------------------------
// Kernel C: quarter 1x1 offset conv (fp32). 128 blocks of 64 pixels.
// ---------------------------------------------------------------------------
__global__ void __launch_bounds__(256) offset_q(
    const float* __restrict__ x,
    const float* __restrict__ w,
    const float* __restrict__ bias,
    int pbbase)
{
    __shared__ float xs[16][64];
    __shared__ float ws[72][16];

    const int t    = threadIdx.x;
    const int pix0 = pbbase * 128 + blockIdx.x * 64;
    const int b    = pix0 >> 14;
    const int rem  = pix0 & (HW_-1);
    const int hh   = rem >> 7;
    const int w0   = rem & (W_-1);

    const int p  = t & 63;
    const int oq = t >> 6;

    float acc[18];
#pragma unroll
    for (int i = 0; i < 18; i++) acc[i] = 0.f;

    const float* xbase = x + (size_t)b * CIN_ * HW_ + hh * W_ + w0;

    for (int c0 = 0; c0 < CIN_; c0 += 16) {
#pragma unroll
        for (int r = 0; r < 4; r++) {
            int e  = t + r * 256;
            int kk = e >> 6;
            int pp = e & 63;
            xs[kk][pp] = xbase[(size_t)(c0 + kk) * HW_ + pp];
        }
        for (int e = t; e < 72 * 16; e += 256) {
            int o  = e >> 4;
            int kk = e & 15;
            ws[o][kk] = w[o * CIN_ + c0 + kk];
        }
        __syncthreads();
#pragma unroll
        for (int kk = 0; kk < 16; kk++) {
            float xv = xs[kk][p];
#pragma unroll
            for (int i = 0; i < 18; i++)
                acc[i] = fmaf(xv, ws[oq * 18 + i][kk], acc[i]);
        }
        __syncthreads();
    }

    float* ob = g_offset + (size_t)(pix0 + p) * OCH_;
#pragma unroll
    for (int i = 0; i < 18; i++) {
        int o = oq * 18 + i;
        ob[o] = acc[i] + bias[o];
    }
}

// ---------------------------------------------------------------------------
// Kernel D: quarter sampler — bilinear gather + bf16 hi/lo split, SW128
// swizzled A-tiles to gmem. grid = (64 pixtiles, 36 chunks), 256 threads.
// ---------------------------------------------------------------------------
__global__ void __launch_bounds__(256) sample_q(const float* __restrict__ xt,
                                                int pbbase)
{
    __shared__ int   sidx[4*128];
    __shared__ float swgt[4*128];

    const int t  = threadIdx.x;
    const int pb = pbbase + blockIdx.x;
    const int gt = blockIdx.y;
    const int pix0 = pb * 128;
    const int b    = pix0 >> 14;
    const int hw0  = pix0 & (HW_-1);
    const int hh   = hw0 >> 7;

    const int g   = gt / 9;
    const int tap = gt - 9*g;
    const int ti  = tap / 3;
    const int tj  = tap - 3*ti;
    const int gch = g * 64;

    if (t < 128) {
        const float* op = g_offset + (size_t)(pix0 + t) * OCH_ + gt*2;
        float ys = (float)(hh - 1 + ti) + op[0];
        float xs = (float)(t  - 1 + tj) + op[1];
        float y0f = floorf(ys), x0f = floorf(xs);
        int   y0  = (int)y0f,   x0  = (int)x0f;
        float ly = ys - y0f, lx = xs - x0f;
        float hy = 1.f - ly, hx = 1.f - lx;
        int y1 = y0 + 1, x1 = x0 + 1;
        bool vy0 = (unsigned)y0 < H_, vy1 = (unsigned)y1 < H_;
        bool vx0 = (unsigned)x0 < W_, vx1 = (unsigned)x1 < W_;
        int cy0 = min(max(y0,0),H_-1), cy1 = min(max(y1,0),H_-1);
        int cx0 = min(max(x0,0),W_-1), cx1 = min(max(x1,0),W_-1);
        sidx[0*128 + t] = cy0*W_ + cx0;
        sidx[1*128 + t] = cy0*W_ + cx1;
        sidx[2*128 + t] = cy1*W_ + cx0;
        sidx[3*128 + t] = cy1*W_ + cx1;
        swgt[0*128 + t] = (vy0 && vx0) ? hy*hx : 0.f;
        swgt[1*128 + t] = (vy0 && vx1) ? hy*lx : 0.f;
        swgt[2*128 + t] = (vy1 && vx0) ? ly*hx : 0.f;
        swgt[3*128 + t] = (vy1 && vx1) ? ly*lx : 0.f;
    }
    __syncthreads();

    const float* xb = xt + (size_t)b * HW_ * CIN_;
    const int slot = t & 15;
    const int gp   = t >> 4;

    char* outh = (char*)g_ah + ((size_t)gt*NPB + pb) * 16384;
    char* outl = (char*)g_al + ((size_t)gt*NPB + pb) * 16384;

#pragma unroll
    for (int pass = 0; pass < 8; pass++) {
        const int p  = pass*16 + gp;
        const int i0 = sidx[0*128+p], i1 = sidx[1*128+p];
        const int i2 = sidx[2*128+p], i3 = sidx[3*128+p];
        const float w0 = swgt[0*128+p], w1 = swgt[1*128+p];
        const float w2 = swgt[2*128+p], w3 = swgt[3*128+p];
        const int co = gch + slot*4;
        float4 v0 = *(const float4*)(xb + (size_t)i0*CIN_ + co);
        float4 v1 = *(const float4*)(xb + (size_t)i1*CIN_ + co);
        float4 v2 = *(const float4*)(xb + (size_t)i2*CIN_ + co);
        float4 v3 = *(const float4*)(xb + (size_t)i3*CIN_ + co);
        float r0 = fmaf(w3,v3.x, fmaf(w2,v2.x, fmaf(w1,v1.x, w0*v0.x)));
        float r1 = fmaf(w3,v3.y, fmaf(w2,v2.y, fmaf(w1,v1.y, w0*v0.y)));
        float r2 = fmaf(w3,v3.z, fmaf(w2,v2.z, fmaf(w1,v1.z, w0*v0.z)));
        float r3 = fmaf(w3,v3.w, fmaf(w2,v2.w, fmaf(w1,v1.w, w0*v0.w)));

        __nv_bfloat16 h0 = __float2bfloat16_rn(r0);
        __nv_bfloat16 h1 = __float2bfloat16_rn(r1);
        __nv_bfloat16 h2 = __float2bfloat16_rn(r2);
        __nv_bfloat16 h3 = __float2bfloat16_rn(r3);
        __nv_bfloat16 l0 = __float2bfloat16_rn(r0 - __bfloat162float(h0));
        __nv_bfloat16 l1 = __float2bfloat16_rn(r1 - __bfloat162float(h1));
        __nv_bfloat16 l2 = __float2bfloat16_rn(r2 - __bfloat162float(h2));
        __nv_bfloat16 l3 = __float2bfloat16_rn(r3 - __bfloat162float(h3));

        const uint32_t off = (uint32_t)(p*128 + ((slot*8) ^ ((p & 7) << 4)));
        __nv_bfloat162 hA(h0, h1), hB(h2, h3), lA(l0, l1), lB(l2, l3);
        uint2 hv, lv;
        hv.x = *(uint32_t*)&hA; hv.y = *(uint32_t*)&hB;
        lv.x = *(uint32_t*)&lA; lv.y = *(uint32_t*)&lB;
        *(uint2*)(outh + off) = hv;
        *(uint2*)(outl + off) = lv;
    }
}

// ---------------------------------------------------------------------------
// Kernel E: quarter GEMM on HMMA (exact R9 config). 64 CTAs, 512 threads.
// 2-stage bulk-copy pipeline; LDSM fragment-reuse order.
// Stage = Ah 16K | Al 16K | Bh 32K | Bl 32K = 96KB.
// ---------------------------------------------------------------------------
#define GS_AH 0
#define GS_AL 16384
#define GS_BH 32768
#define GS_BL 65536
#define GSTAGE 98304
#define GS_MBAR (2*GSTAGE)
#define GSMEM (2*GSTAGE + 32)

__device__ __forceinline__ void gemm_issue_bulk(uint32_t sbase, uint32_t mbar,
                                                int gt, int pb,
                                                const __nv_bfloat16* wb)
{
    const char* ah = (const char*)g_ah + ((size_t)gt*NPB + pb) * 16384;
    const char* al = (const char*)g_al + ((size_t)gt*NPB + pb) * 16384;
    const char* bs = (const char*)wb + (size_t)gt * 65536;
    mbar_expect_tx(mbar, GSTAGE);
    bulk_copy(sbase + GS_AH, ah, 16384, mbar);
    bulk_copy(sbase + GS_AL, al, 16384, mbar);
    bulk_copy(sbase + GS_BH, bs, 65536, mbar);
}

__global__ void __launch_bounds__(512, 1)
gemm_q(const __nv_bfloat16* __restrict__ wb, float* __restrict__ out, int pbbase)
{
    extern __shared__ char sm[];
    const uint32_t sb = smem_u32(sm);

    const int t = threadIdx.x;
    const int warp = t >> 5, lane = t & 31;
    const int pb   = pbbase + blockIdx.x;
    const int pix0 = pb * 128;
    const int b    = pix0 >> 14;
    const int hw0  = pix0 & (HW_-1);

    if (t == 0) {
        mbar_init(sb + GS_MBAR, 1);
        mbar_init(sb + GS_MBAR + 8, 1);
    }
    __syncthreads();

    const int wm = warp & 3, wn = warp >> 2;

    const uint32_t rowA = wm*32 + (lane & 15);
    const uint32_t swzA = (rowA & 7) << 4;
    const uint32_t kA   = (uint32_t)(lane & 16);
    const uint32_t aRow = rowA * 128;

    const uint32_t rowB = wn*64 + (lane & 7) + ((lane & 16) >> 1);
    const uint32_t swzB = (rowB & 7) << 4;
    const uint32_t kB   = (uint32_t)((lane & 8) << 1);
    const uint32_t bRow = rowB * 128;

    float acc[2][8][4];
#pragma unroll
    for (int i = 0; i < 2; i++)
#pragma unroll
        for (int j = 0; j < 8; j++)
#pragma unroll
            for (int q = 0; q < 4; q++) acc[i][j][q] = 0.f;

    if (t == 0) gemm_issue_bulk(sb, sb + GS_MBAR, 0, pb, wb);

    for (int gt = 0; gt < NCHUNK; gt++) {
        const int s = gt & 1;
        const uint32_t cur = sb + s * GSTAGE;
        if (gt + 1 < NCHUNK && t == 0)
            gemm_issue_bulk(sb + ((gt + 1) & 1) * GSTAGE,
                            sb + GS_MBAR + ((gt + 1) & 1) * 8, gt + 1, pb, wb);

        mbar_wait(sb + GS_MBAR + s * 8, (gt >> 1) & 1);

#pragma unroll
        for (int ks = 0; ks < 4; ks++) {
            const uint32_t kbyte = (uint32_t)(ks * 32);
            const uint32_t aoff = (kbyte + kA) ^ swzA;
            const uint32_t boff = (kbyte + kB) ^ swzB;

            uint32_t bfr[4][4], ah[2][4], al[2][4];

#pragma unroll
            for (int np = 0; np < 4; np++)
                ldsm_x4(bfr[np], cur + GS_BH + bRow + np*2048 + boff);
#pragma unroll
            for (int mt = 0; mt < 2; mt++)
                ldsm_x4(ah[mt], cur + GS_AH + aRow + mt*2048 + aoff);

#pragma unroll
            for (int mt = 0; mt < 2; mt++)
#pragma unroll
                for (int nt = 0; nt < 8; nt++)
                    mma_bf16(acc[mt][nt], ah[mt],
                             bfr[nt >> 1][(nt & 1) * 2],
                             bfr[nt >> 1][(nt & 1) * 2 + 1]);

#pragma unroll
            for (int mt = 0; mt < 2; mt++)
                ldsm_x4(al[mt], cur + GS_AL + aRow + mt*2048 + aoff);
#pragma unroll
            for (int mt = 0; mt < 2; mt++)
#pragma unroll
                for (int nt = 0; nt < 8; nt++)
                    mma_bf16(acc[mt][nt], al[mt],
                             bfr[nt >> 1][(nt & 1) * 2],
                             bfr[nt >> 1][(nt & 1) * 2 + 1]);

#pragma unroll
            for (int np = 0; np < 4; np++)
                ldsm_x4(bfr[np], cur + GS_BL + bRow + np*2048 + boff);
#pragma unroll
            for (int mt = 0; mt < 2; mt++)
#pragma unroll
                for (int nt = 0; nt < 8; nt++)
                    mma_bf16(acc[mt][nt], ah[mt],
                             bfr[nt >> 1][(nt & 1) * 2],
                             bfr[nt >> 1][(nt & 1) * 2 + 1]);
        }
        __syncthreads();
    }

    // epilogue: relu + store (NCHW)
    const size_t ob = (size_t)b * COUT_ * HW_ + hw0;
    const int mrow = wm*32 + (lane >> 2);
    const int ncol = wn*64 + (lane & 3) * 2;
#pragma unroll
    for (int mt = 0; mt < 2; mt++) {
#pragma unroll
        for (int nt = 0; nt < 8; nt++) {
            const int m = mrow + mt*16;
            const int n = ncol + nt*8;
            float* o0 = out + ob + (size_t)n * HW_ + m;
            o0[0]        = fmaxf(acc[mt][nt][0], 0.f);
            o0[HW_]      = fmaxf(acc[mt][nt][1], 0.f);
            o0[8]        = fmaxf(acc[mt][nt][2], 0.f);
            o0[HW_ + 8]  = fmaxf(acc[mt][nt][3], 0.f);
        }
    }
}

// ---------------------------------------------------------------------------
// Host: 4-way pipelined launch (fork/join via events; capture-safe)
// ---------------------------------------------------------------------------
extern "C" void kernel_launch(void* const* d_in, const int* in_sizes, int n_in,
                              void* d_out, int out_size)
{
    (void)in_sizes; (void)n_in; (void)out_size;
    const float* x     = (const float*)d_in[0];
    const float* w_off = (const float*)d_in[1];
    const float* b_off = (const float*)d_in[2];
    const float* w_def = (const float*)d_in[3];
    float* out = (float*)d_out;

    float* xt;           cudaGetSymbolAddress((void**)&xt, g_xt);
    __nv_bfloat16* wbp;  cudaGetSymbolAddress((void**)&wbp, g_wb);

    static cudaStream_t st[3];
    static cudaEvent_t evRoot, evPP, evDone[3];
    static bool init = false;
    if (!init) {
        for (int i = 0; i < 3; i++)
            cudaStreamCreateWithFlags(&st[i], cudaStreamNonBlocking);
        cudaEventCreateWithFlags(&evRoot, cudaEventDisableTiming);
        cudaEventCreateWithFlags(&evPP,   cudaEventDisableTiming);
        for (int i = 0; i < 3; i++)
            cudaEventCreateWithFlags(&evDone[i], cudaEventDisableTiming);
        cudaFuncSetAttribute(gemm_q,
                             cudaFuncAttributeMaxDynamicSharedMemorySize, GSMEM);
        init = true;
    }

    // fork
    cudaEventRecord(evRoot, 0);
    for (int i = 0; i < 3; i++) cudaStreamWaitEvent(st[i], evRoot, 0);

    // prepack first on the base stream; gemms on side streams wait evPP
    prepack_kernel<<<NCHUNK, 256>>>(w_def, wbp);
    cudaEventRecord(evPP, 0);

    // pipeline 0 on base stream
    transpose_q<<<dim3(256, 8), dim3(32, 8)>>>(x, xt, 0);
    offset_q<<<128, 256>>>(x, w_off, b_off, 0);
    sample_q<<<dim3(QPB, NCHUNK), 256>>>(xt, 0);
    gemm_q<<<QPB, 512, GSMEM>>>(wbp, out, 0);

    // pipelines 1..3 on side streams
    for (int q = 1; q < 4; q++) {
        cudaStream_t s = st[q - 1];
        const int pbbase = q * QPB;
        transpose_q<<<dim3(256, 8), dim3(32, 8), 0, s>>>(x, xt, pbbase);
        offset_q<<<128, 256, 0, s>>>(x, w_off, b_off, pbbase);
        sample_q<<<dim3(QPB, NCHUNK), 256, 0, s>>>(xt, pbbase);
        cudaStreamWaitEvent(s, evPP, 0);
        gemm_q<<<QPB, 512, GSMEM, s>>>(wbp, out, pbbase);
        cudaEventRecord(evDone[q - 1], s);
    }

    // join
    for (int i = 0; i < 3; i++) cudaStreamWaitEvent(0, evDone[i], 0);
}

// round 17
// speedup vs baseline: 1.3181x; 1.1406x over previous
#include <cuda_runtime.h>
#include <cuda_bf16.h>
#include <cstdint>

#define B_    2
#define CIN_  256
#define COUT_ 256
#define H_    128
#define W_    128
#define HW_   (H_*W_)
#define KK_   3
#define G_    4
#define OCH_  (G_*2*KK_*KK_)   // 72
#define KRED  (CIN_*KK_*KK_)   // 2304
#define NCHUNK (G_*KK_*KK_)    // 36 chunks of 64 k each
#define NPB   (B_*HW_/128)     // 256 pixel tiles
#define QPB   (NPB/4)          // 64 tiles per quarter

// Scratch buffers
__device__ float    g_offset[B_*HW_*OCH_];                 // [pix][72]
__device__ float    g_xt[(size_t)B_*HW_*CIN_];             // NHWC: [b][hw][c]
__device__ uint32_t g_wbf[(size_t)NCHUNK*16384];           // per chunk: 64KB tf32 [n][k] swizzled
__device__ uint32_t g_a[(size_t)NCHUNK*NPB*8192];          // per (chunk,pb): 32KB tf32 [p][k] swizzled

// ---------------------------------------------------------------------------
// helpers
// ---------------------------------------------------------------------------
__device__ __forceinline__ uint32_t smem_u32(const void* p) {
    uint32_t a;
    asm("{ .reg .u64 t; cvta.to.shared.u64 t, %1; cvt.u32.u64 %0, t; }" : "=r"(a) : "l"(p));
    return a;
}
__device__ __forceinline__ uint32_t f2tf32(float x) {
    uint32_t u;
    asm("cvt.rna.tf32.f32 %0, %1;" : "=r"(u) : "f"(x));
    return u;
}
__device__ __forceinline__ void mma_tf32(float d[4], const uint32_t a[4],
                                         uint32_t b0, uint32_t b1) {
    asm volatile(
        "mma.sync.aligned.m16n8k8.row.col.f32.tf32.tf32.f32 "
        "{%0,%1,%2,%3}, {%4,%5,%6,%7}, {%8,%9}, {%0,%1,%2,%3};"
        : "+f"(d[0]), "+f"(d[1]), "+f"(d[2]), "+f"(d[3])
        : "r"(a[0]), "r"(a[1]), "r"(a[2]), "r"(a[3]), "r"(b0), "r"(b1));
}
__device__ __forceinline__ void mbar_init(uint32_t mbar, uint32_t cnt) {
    asm volatile("mbarrier.init.shared.b64 [%0], %1;" :: "r"(mbar), "r"(cnt) : "memory");
}
__device__ __forceinline__ void mbar_expect_tx(uint32_t mbar, uint32_t bytes) {
    asm volatile("mbarrier.arrive.expect_tx.shared.b64 _, [%0], %1;"
                 :: "r"(mbar), "r"(bytes) : "memory");
}
__device__ __forceinline__ void mbar_wait(uint32_t mbar, uint32_t parity) {
    asm volatile(
        "{\n\t.reg .pred P;\n\t"
        "WL_%=:\n\t"
        "mbarrier.try_wait.parity.acquire.cta.shared::cta.b64 P, [%0], %1, 0x989680;\n\t"
        "@P bra.uni WD_%=;\n\t"
        "bra.uni WL_%=;\n\t"
        "WD_%=:\n\t}"
        :: "r"(mbar), "r"(parity) : "memory");
}
__device__ __forceinline__ void bulk_copy(uint32_t dst, const void* src, uint32_t bytes,
                                          uint32_t mbar) {
    asm volatile(
        "cp.async.bulk.shared::cta.global.mbarrier::complete_tx::bytes [%0], [%1], %2, [%3];"
        :: "r"(dst), "l"(src), "r"(bytes), "r"(mbar) : "memory");
}

// ---------------------------------------------------------------------------
// Kernel A: quarter transpose NCHW -> NHWC (32x32 tiles).
// ---------------------------------------------------------------------------
__global__ void __launch_bounds__(256) transpose_q(const float* __restrict__ x,
                                                   float* __restrict__ xt,
                                                   int pbbase)
{
    __shared__ float tl[32][33];
    const int tx = threadIdx.x, ty = threadIdx.y;
    const int bb    = pbbase >> 7;
    const int hwqb  = (pbbase * 128) & (HW_-1);
    const int hw0 = hwqb + blockIdx.x * 32;
    const int c0  = blockIdx.y * 32;
#pragma unroll
    for (int r = 0; r < 4; r++)
        tl[ty + 8*r][tx] = x[((size_t)bb*CIN_ + c0 + ty + 8*r)*HW_ + hw0 + tx];
    __syncthreads();
#pragma unroll
    for (int r = 0; r < 4; r++)
        xt[((size_t)bb*HW_ + hw0 + ty + 8*r)*CIN_ + c0 + tx] = tl[tx][ty + 8*r];
}

// ---------------------------------------------------------------------------
// Kernel B: weight prepack -> tf32, [n][k] tiles, XOR-swizzled (k ^ (n&7)<<2).
// ---------------------------------------------------------------------------
__global__ void __launch_bounds__(256) prepack_kernel(const float* __restrict__ wd,
                                                      uint32_t* __restrict__ wb)
{
    const int gt = blockIdx.x;
    const int g = gt / 9;
    const int tap = gt - 9*g;
    for (int idx = threadIdx.x; idx < 256*64; idx += 256) {
        const int n  = idx >> 6;
        const int cg = idx & 63;
        float v = wd[(size_t)n*KRED + (g*64 + cg)*9 + tap];
        wb[(size_t)gt*16384 + n*64 + (cg ^ ((n & 7) << 2))] = f2tf32(v);
    }
}

// ---------------------------------------------------------------------------
// Kernel C: quarter 1x1 offset conv (fp32).
// ---------------------------------------------------------------------------
__global__ void __launch_bounds__(256) offset_q(
    const float* __restrict__ x,
    const float* __restrict__ w,
    const float* __restrict__ bias,
    int pbbase)
{
    __shared__ float xs[16][64];
    __shared__ float ws[72][16];

    const int t    = threadIdx.x;
    const int pix0 = pbbase * 128 + blockIdx.x * 64;
    const int b    = pix0 >> 14;
    const int rem  = pix0 & (HW_-1);
    const int hh   = rem >> 7;
    const int w0   = rem & (W_-1);

    const int p  = t & 63;
    const int oq = t >> 6;

    float acc[18];
#pragma unroll
    for (int i = 0; i < 18; i++) acc[i] = 0.f;

    const float* xbase = x + (size_t)b * CIN_ * HW_ + hh * W_ + w0;

    for (int c0 = 0; c0 < CIN_; c0 += 16) {
#pragma unroll
        for (int r = 0; r < 4; r++) {
            int e  = t + r * 256;
            int kk = e >> 6;
            int pp = e & 63;
            xs[kk][pp] = xbase[(size_t)(c0 + kk) * HW_ + pp];
        }
        for (int e = t; e < 72 * 16; e += 256) {
            int o  = e >> 4;
            int kk = e & 15;
            ws[o][kk] = w[o * CIN_ + c0 + kk];
        }
        __syncthreads();
#pragma unroll
        for (int kk = 0; kk < 16; kk++) {
            float xv = xs[kk][p];
#pragma unroll
            for (int i = 0; i < 18; i++)
                acc[i] = fmaf(xv, ws[oq * 18 + i][kk], acc[i]);
        }
        __syncthreads();
    }

    float* ob = g_offset + (size_t)(pix0 + p) * OCH_;
#pragma unroll
    for (int i = 0; i < 18; i++) {
        int o = oq * 18 + i;
        ob[o] = acc[i] + bias[o];
    }
}

// ---------------------------------------------------------------------------
// Kernel D: quarter sampler — bilinear gather, tf32 convert, swizzled
// 32KB A-tiles to gmem. grid = (64 pixtiles, 36 chunks), 256 threads.
// ---------------------------------------------------------------------------
__global__ void __launch_bounds__(256) sample_q(const float* __restrict__ xt,
                                                int pbbase)
{
    __shared__ int   sidx[4*128];
    __shared__ float swgt[4*128];

    const int t  = threadIdx.x;
    const int pb = pbbase + blockIdx.x;
    const int gt = blockIdx.y;
    const int pix0 = pb * 128;
    const int b    = pix0 >> 14;
    const int hw0  = pix0 & (HW_-1);
    const int hh   = hw0 >> 7;

    const int g   = gt / 9;
    const int tap = gt - 9*g;
    const int ti  = tap / 3;
    const int tj  = tap - 3*ti;
    const int gch = g * 64;

    if (t < 128) {
        const float* op = g_offset + (size_t)(pix0 + t) * OCH_ + gt*2;
        float ys = (float)(hh - 1 + ti) + op[0];
        float xs = (float)(t  - 1 + tj) + op[1];
        float y0f = floorf(ys), x0f = floorf(xs);
        int   y0  = (int)y0f,   x0  = (int)x0f;
        float ly = ys - y0f, lx = xs - x0f;
        float hy = 1.f - ly, hx = 1.f - lx;
        int y1 = y0 + 1, x1 = x0 + 1;
        bool vy0 = (unsigned)y0 < H_, vy1 = (unsigned)y1 < H_;
        bool vx0 = (unsigned)x0 < W_, vx1 = (unsigned)x1 < W_;
        int cy0 = min(max(y0,0),H_-1), cy1 = min(max(y1,0),H_-1);
        int cx0 = min(max(x0,0),W_-1), cx1 = min(max(x1,0),W_-1);
        sidx[0*128 + t] = cy0*W_ + cx0;
        sidx[1*128 + t] = cy0*W_ + cx1;
        sidx[2*128 + t] = cy1*W_ + cx0;
        sidx[3*128 + t] = cy1*W_ + cx1;
        swgt[0*128 + t] = (vy0 && vx0) ? hy*hx : 0.f;
        swgt[1*128 + t] = (vy0 && vx1) ? hy*lx : 0.f;
        swgt[2*128 + t] = (vy1 && vx0) ? ly*hx : 0.f;
        swgt[3*128 + t] = (vy1 && vx1) ? ly*lx : 0.f;
    }
    __syncthreads();

    const float* xb = xt + (size_t)b * HW_ * CIN_;
    const int slot = t & 15;
    const int gp   = t >> 4;

    char* outa = (char*)g_a + ((size_t)gt*NPB + pb) * 32768;

#pragma unroll
    for (int pass = 0; pass < 8; pass++) {
        const int p  = pass*16 + gp;
        const int i0 = sidx[0*128+p], i1 = sidx[1*128+p];
        const int i2 = sidx[2*128+p], i3 = sidx[3*128+p];
        const float w0 = swgt[0*128+p], w1 = swgt[1*128+p];
        const float w2 = swgt[2*128+p], w3 = swgt[3*128+p];
        const int co = gch + slot*4;
        float4 v0 = *(const float4*)(xb + (size_t)i0*CIN_ + co);
        float4 v1 = *(const float4*)(xb + (size_t)i1*CIN_ + co);
        float4 v2 = *(const float4*)(xb + (size_t)i2*CIN_ + co);
        float4 v3 = *(const float4*)(xb + (size_t)i3*CIN_ + co);
        float r0 = fmaf(w3,v3.x, fmaf(w2,v2.x, fmaf(w1,v1.x, w0*v0.x)));
        float r1 = fmaf(w3,v3.y, fmaf(w2,v2.y, fmaf(w1,v1.y, w0*v0.y)));
        float r2 = fmaf(w3,v3.z, fmaf(w2,v2.z, fmaf(w1,v1.z, w0*v0.z)));
        float r3 = fmaf(w3,v3.w, fmaf(w2,v2.w, fmaf(w1,v1.w, w0*v0.w)));

        // swizzled store: byte off = p*256 + ((slot*16) ^ ((p&7)*16))
        const uint32_t off = (uint32_t)(p*256 + ((slot*16) ^ ((p & 7) << 4)));
        *(uint4*)(outa + off) = make_uint4(f2tf32(r0), f2tf32(r1),
                                           f2tf32(r2), f2tf32(r3));
    }
}

// ---------------------------------------------------------------------------
// Kernel E: quarter GEMM on tf32 HMMA, single pass.
// 128 pix x 256 cout per block, 512 threads (16 warps = 4m x 4n, warp 32x64).
// 2-stage bulk-copy pipeline. Stage = A 32K | B 64K = 96KB.
// Fragments via conflict-free XOR-swizzled scalar LDS.32.
// ---------------------------------------------------------------------------
#define GS_A  0
#define GS_B  32768
#define GSTAGE 98304
#define GS_MBAR (2*GSTAGE)
#define GSMEM (2*GSTAGE + 32)

__device__ __forceinline__ void gemm_issue_bulk(uint32_t sbase, uint32_t mbar,
                                                int gt, int pb,
                                                const uint32_t* wb)
{
    const char* as = (const char*)g_a + ((size_t)gt*NPB + pb) * 32768;
    const char* bs = (const char*)wb + (size_t)gt * 65536;
    mbar_expect_tx(mbar, 98304);
    bulk_copy(sbase + GS_A, as, 32768, mbar);
    bulk_copy(sbase + GS_B, bs, 65536, mbar);
}

__global__ void __launch_bounds__(512, 1)
gemm_q(const uint32_t* __restrict__ wb, float* __restrict__ out, int pbbase)
{
    extern __shared__ char sm[];
    const uint32_t sb = smem_u32(sm);

    const int t = threadIdx.x;
    const int warp = t >> 5, lane = t & 31;
    const int pb   = pbbase + blockIdx.x;
    const int pix0 = pb * 128;
    const int b    = pix0 >> 14;
    const int hw0  = pix0 & (HW_-1);

    if (t == 0) {
        mbar_init(sb + GS_MBAR, 1);
        mbar_init(sb + GS_MBAR + 8, 1);
    }
    __syncthreads();

    const int wm = warp & 3, wn = warp >> 2;

    // fragment geometry (m16n8k8 tf32)
    const uint32_t sw4 = (uint32_t)((lane & 28) << 2);      // byte XOR = 4*((lane>>2)<<2)
    const uint32_t kb0 = (uint32_t)((lane & 3) << 2);       // byte offset of k low part
    uint32_t aRowOff[2], bRowOff[8];
#pragma unroll
    for (int mt = 0; mt < 2; mt++)
        aRowOff[mt] = (uint32_t)((wm*32 + mt*16 + (lane >> 2)) * 256);
#pragma unroll
    for (int nt = 0; nt < 8; nt++)
        bRowOff[nt] = (uint32_t)((wn*64 + nt*8 + (lane >> 2)) * 256);

    float acc[2][8][4];
#pragma unroll
    for (int i = 0; i < 2; i++)
#pragma unroll
        for (int j = 0; j < 8; j++)
#pragma unroll
            for (int q = 0; q < 4; q++) acc[i][j][q] = 0.f;

    if (t == 0) gemm_issue_bulk(sb, sb + GS_MBAR, 0, pb, wb);

    for (int gt = 0; gt < NCHUNK; gt++) {
        const int s = gt & 1;
        const char* smA = sm + s * GSTAGE + GS_A;
        const char* smB = sm + s * GSTAGE + GS_B;
        if (gt + 1 < NCHUNK && t == 0)
            gemm_issue_bulk(sb + ((gt + 1) & 1) * GSTAGE,
                            sb + GS_MBAR + ((gt + 1) & 1) * 8, gt + 1, pb, wb);

        mbar_wait(sb + GS_MBAR + s * 8, (gt >> 1) & 1);

        // 8 k-steps of k8 tf32
#pragma unroll
        for (int ks = 0; ks < 8; ks++) {
            const uint32_t kz0 = (kb0 + (uint32_t)(ks << 5)) ^ sw4;  // bytes
            const uint32_t kz1 = kz0 ^ 16;

            uint32_t bfr[8][2];
#pragma unroll
            for (int nt = 0; nt < 8; nt++) {
                bfr[nt][0] = *(const uint32_t*)(smB + bRowOff[nt] + kz0);
                bfr[nt][1] = *(const uint32_t*)(smB + bRowOff[nt] + kz1);
            }
            uint32_t afr[2][4];
#pragma unroll
            for (int mt = 0; mt < 2; mt++) {
                const char* ab = smA + aRowOff[mt];
                afr[mt][0] = *(const uint32_t*)(ab + kz0);
                afr[mt][1] = *(const uint32_t*)(ab + 2048 + kz0);
                afr[mt][2] = *(const uint32_t*)(ab + kz1);
                afr[mt][3] = *(const uint32_t*)(ab + 2048 + kz1);
            }
#pragma unroll
            for (int mt = 0; mt < 2; mt++)
#pragma unroll
                for (int nt = 0; nt < 8; nt++)
                    mma_tf32(acc[mt][nt], afr[mt], bfr[nt][0], bfr[nt][1]);
        }
        __syncthreads();
    }

    // epilogue: relu + store (NCHW)
    const size_t ob = (size_t)b * COUT_ * HW_ + hw0;
    const int mrow = wm*32 + (lane >> 2);
    const int ncol = wn*64 + (lane & 3) * 2;
#pragma unroll
    for (int mt = 0; mt < 2; mt++) {
#pragma unroll
        for (int nt = 0; nt < 8; nt++) {
            const int m = mrow + mt*16;
            const int n = ncol + nt*8;
            float* o0 = out + ob + (size_t)n * HW_ + m;
            o0[0]        = fmaxf(acc[mt][nt][0], 0.f);
            o0[HW_]      = fmaxf(acc[mt][nt][1], 0.f);
            o0[8]        = fmaxf(acc[mt][nt][2], 0.f);
            o0[HW_ + 8]  = fmaxf(acc[mt][nt][3], 0.f);
        }
    }
}

// ---------------------------------------------------------------------------
// Host: 4-way pipelined launch (identical structure to the passing R15)
// ---------------------------------------------------------------------------
extern "C" void kernel_launch(void* const* d_in, const int* in_sizes, int n_in,
                              void* d_out, int out_size)
{
    (void)in_sizes; (void)n_in; (void)out_size;
    const float* x     = (const float*)d_in[0];
    const float* w_off = (const float*)d_in[1];
    const float* b_off = (const float*)d_in[2];
    const float* w_def = (const float*)d_in[3];
    float* out = (float*)d_out;

    float* xt;      cudaGetSymbolAddress((void**)&xt, g_xt);
    uint32_t* wbp;  cudaGetSymbolAddress((void**)&wbp, g_wbf);

    static cudaStream_t st[3];
    static cudaEvent_t evRoot, evPP, evDone[3];
    static bool init = false;
    if (!init) {
        for (int i = 0; i < 3; i++)
            cudaStreamCreateWithFlags(&st[i], cudaStreamNonBlocking);
        cudaEventCreateWithFlags(&evRoot, cudaEventDisableTiming);
        cudaEventCreateWithFlags(&evPP,   cudaEventDisableTiming);
        for (int i = 0; i < 3; i++)
            cudaEventCreateWithFlags(&evDone[i], cudaEventDisableTiming);
        cudaFuncSetAttribute(gemm_q,
                             cudaFuncAttributeMaxDynamicSharedMemorySize, GSMEM);
        init = true;
    }

    // fork
    cudaEventRecord(evRoot, 0);
    for (int i = 0; i < 3; i++) cudaStreamWaitEvent(st[i], evRoot, 0);

    // prepack first on the base stream; gemms on side streams wait evPP
    prepack_kernel<<<NCHUNK, 256>>>(w_def, wbp);
    cudaEventRecord(evPP, 0);

    // pipeline 0 on base stream
    transpose_q<<<dim3(256, 8), dim3(32, 8)>>>(x, xt, 0);
    offset_q<<<128, 256>>>(x, w_off, b_off, 0);
    sample_q<<<dim3(QPB, NCHUNK), 256>>>(xt, 0);
    gemm_q<<<QPB, 512, GSMEM>>>(wbp, out, 0);

    // pipelines 1..3 on side streams
    for (int q = 1; q < 4; q++) {
        cudaStream_t s = st[q - 1];
        const int pbbase = q * QPB;
        transpose_q<<<dim3(256, 8), dim3(32, 8), 0, s>>>(x, xt, pbbase);
        offset_q<<<128, 256, 0, s>>>(x, w_off, b_off, pbbase);
        sample_q<<<dim3(QPB, NCHUNK), 256, 0, s>>>(xt, pbbase);
        cudaStreamWaitEvent(s, evPP, 0);
        gemm_q<<<QPB, 512, GSMEM, s>>>(wbp, out, pbbase);
        cudaEventRecord(evDone[q - 1], s);
    }

    // join
    for (int i = 0; i < 3; i++) cudaStreamWaitEvent(0, evDone[i], 0);
}